// round 1
// baseline (speedup 1.0000x reference)
#include <cuda_runtime.h>

#define NB 4
#define NT 4096
#define NC 1024
#define NH 16
#define ND 64
#define NM (NB*NT)          // 16384 rows
#define KVSPLIT 8

// Scratch (allocation-free requirement -> device globals)
__device__ float g_Q[(size_t)NM*NC];
__device__ float g_K[(size_t)NM*NC];
__device__ float g_V[(size_t)NM*NC];
__device__ float g_A[(size_t)NM*NC];
__device__ float g_KV[NB*NH*ND*ND];
__device__ float g_KS[NB*NH*ND];

// ---------------------------------------------------------------------------
// GEMM body: C[m,n] = sum_k A[m,k] * W[n,k] + bias[n]
// M=NM (by grid.y), N=NC (by grid.x), K=NC. 128x128 block tile, BK=16,
// 8x8 per-thread register tile, 256 threads.
// ---------------------------------------------------------------------------
__device__ __forceinline__ void gemm_body(
    const float* __restrict__ A, const float* __restrict__ W,
    const float* __restrict__ bias, float* __restrict__ C)
{
    constexpr int BM = 128, BN = 128, BK = 16;
    constexpr int K = NC, N = NC;
    __shared__ float As[BK][BM + 4];
    __shared__ float Bs[BK][BN + 4];

    const int tid = threadIdx.x;
    const int ty = tid >> 4;      // 0..15
    const int tx = tid & 15;      // 0..15
    const int m0 = blockIdx.y * BM;
    const int n0 = blockIdx.x * BN;

    float acc[8][8] = {};

    for (int k0 = 0; k0 < K; k0 += BK) {
        // load 128x16 tiles of A and W, store transposed (k-major)
        #pragma unroll
        for (int i = 0; i < 2; i++) {
            int idx = i * 256 + tid;       // 0..511 float4 slots
            int row = idx >> 2;            // 0..127
            int c4  = (idx & 3) << 2;      // 0,4,8,12
            float4 a = *reinterpret_cast<const float4*>(A + (m0 + row) * K + k0 + c4);
            As[c4 + 0][row] = a.x; As[c4 + 1][row] = a.y;
            As[c4 + 2][row] = a.z; As[c4 + 3][row] = a.w;
            float4 b = *reinterpret_cast<const float4*>(W + (n0 + row) * K + k0 + c4);
            Bs[c4 + 0][row] = b.x; Bs[c4 + 1][row] = b.y;
            Bs[c4 + 2][row] = b.z; Bs[c4 + 3][row] = b.w;
        }
        __syncthreads();

        #pragma unroll
        for (int k = 0; k < BK; k++) {
            float ra[8], rb[8];
            #pragma unroll
            for (int i = 0; i < 8; i++) ra[i] = As[k][ty * 8 + i];
            #pragma unroll
            for (int j = 0; j < 8; j++) rb[j] = Bs[k][tx * 8 + j];
            #pragma unroll
            for (int i = 0; i < 8; i++)
                #pragma unroll
                for (int j = 0; j < 8; j++)
                    acc[i][j] = fmaf(ra[i], rb[j], acc[i][j]);
        }
        __syncthreads();
    }

    #pragma unroll
    for (int i = 0; i < 8; i++) {
        int m = m0 + ty * 8 + i;
        #pragma unroll
        for (int j = 0; j < 8; j += 4) {
            int n = n0 + tx * 8 + j;
            float4 o;
            o.x = acc[i][j + 0] + bias[n + 0];
            o.y = acc[i][j + 1] + bias[n + 1];
            o.z = acc[i][j + 2] + bias[n + 2];
            o.w = acc[i][j + 3] + bias[n + 3];
            *reinterpret_cast<float4*>(C + m * N + n) = o;
        }
    }
}

// Fused Q/K/V projection: blockIdx.z selects which GEMM.
__global__ __launch_bounds__(256) void qkv_gemm_kernel(
    const float* __restrict__ x, const float* __restrict__ y,
    const float* __restrict__ Wq, const float* __restrict__ bq,
    const float* __restrict__ Wk, const float* __restrict__ bk,
    const float* __restrict__ Wv, const float* __restrict__ bv)
{
    const float* A    = (blockIdx.z == 0) ? x  : y;
    const float* W    = (blockIdx.z == 0) ? Wq : ((blockIdx.z == 1) ? Wk : Wv);
    const float* bias = (blockIdx.z == 0) ? bq : ((blockIdx.z == 1) ? bk : bv);
    float* C          = (blockIdx.z == 0) ? g_Q : ((blockIdx.z == 1) ? g_K : g_V);
    gemm_body(A, W, bias, C);
}

__global__ __launch_bounds__(256) void proj_gemm_kernel(
    const float* __restrict__ Wp, const float* __restrict__ bp,
    float* __restrict__ out)
{
    gemm_body(g_A, Wp, bp, out);
}

// ---------------------------------------------------------------------------
// Softmax over head-dim 64. Rows (m,h) are contiguous 64-float segments.
// One warp per row, 2 elements per lane. blockIdx.y: 0 -> Q, 1 -> K.
// ---------------------------------------------------------------------------
__global__ __launch_bounds__(256) void softmax_kernel()
{
    int gid  = blockIdx.x * blockDim.x + threadIdx.x;
    int warp = gid >> 5;
    int lane = gid & 31;
    float* p = ((blockIdx.y == 0) ? g_Q : g_K) + (size_t)warp * 64;

    float v0 = p[lane], v1 = p[lane + 32];
    float mx = fmaxf(v0, v1);
    #pragma unroll
    for (int o = 16; o > 0; o >>= 1) mx = fmaxf(mx, __shfl_xor_sync(0xffffffffu, mx, o));
    v0 = __expf(v0 - mx);
    v1 = __expf(v1 - mx);
    float s = v0 + v1;
    #pragma unroll
    for (int o = 16; o > 0; o >>= 1) s += __shfl_xor_sync(0xffffffffu, s, o);
    float inv = 1.f / s;
    p[lane]      = v0 * inv;
    p[lane + 32] = v1 * inv;
}

// ---------------------------------------------------------------------------
// Zero g_KV / g_KS (kv_kernel accumulates with atomics).
// ---------------------------------------------------------------------------
__global__ void zero_kernel()
{
    int i = blockIdx.x * blockDim.x + threadIdx.x;
    if (i < NB * NH * ND * ND) g_KV[i] = 0.f;
    if (i < NB * NH * ND)      g_KS[i] = 0.f;
}

// ---------------------------------------------------------------------------
// kv[d][e] = sum_n K[n,d]*V[n,e]; ksum[d] = sum_n K[n,d].
// One block per (b*h, T-split). 256 threads = 16x16, 4x4 per thread.
// ---------------------------------------------------------------------------
__global__ __launch_bounds__(256) void kv_kernel()
{
    const int bh    = blockIdx.x;
    const int split = blockIdx.y;
    const float* Kp = g_K + (size_t)(bh / NH) * NT * NC + (bh % NH) * ND;
    const float* Vp = g_V + (size_t)(bh / NH) * NT * NC + (bh % NH) * ND;

    __shared__ float Ks[32][ND];
    __shared__ float Vs[32][ND];

    const int tid = threadIdx.x;
    const int ty = tid >> 4, tx = tid & 15;

    float acc[4][4] = {};
    float ksp[4]    = {};

    const int nbase = split * (NT / KVSPLIT);
    for (int it = 0; it < (NT / KVSPLIT) / 32; it++) {
        int n0 = nbase + it * 32;
        #pragma unroll
        for (int i = 0; i < 2; i++) {
            int idx = i * 256 + tid;       // 512 float4 per matrix tile
            int row = idx >> 4;            // 0..31
            int c4  = (idx & 15) << 2;     // 0..60
            *reinterpret_cast<float4*>(&Ks[row][c4]) =
                *reinterpret_cast<const float4*>(Kp + (size_t)(n0 + row) * NC + c4);
            *reinterpret_cast<float4*>(&Vs[row][c4]) =
                *reinterpret_cast<const float4*>(Vp + (size_t)(n0 + row) * NC + c4);
        }
        __syncthreads();
        #pragma unroll 8
        for (int n = 0; n < 32; n++) {
            float ra[4], rb[4];
            #pragma unroll
            for (int i = 0; i < 4; i++) ra[i] = Ks[n][ty * 4 + i];
            #pragma unroll
            for (int j = 0; j < 4; j++) rb[j] = Vs[n][tx * 4 + j];
            #pragma unroll
            for (int i = 0; i < 4; i++)
                #pragma unroll
                for (int j = 0; j < 4; j++)
                    acc[i][j] = fmaf(ra[i], rb[j], acc[i][j]);
            if (tx == 0) {
                #pragma unroll
                for (int i = 0; i < 4; i++) ksp[i] += ra[i];
            }
        }
        __syncthreads();
    }

    float* kvout = g_KV + bh * ND * ND;
    #pragma unroll
    for (int i = 0; i < 4; i++)
        #pragma unroll
        for (int j = 0; j < 4; j++)
            atomicAdd(&kvout[(ty * 4 + i) * ND + tx * 4 + j], acc[i][j]);
    if (tx == 0) {
        #pragma unroll
        for (int i = 0; i < 4; i++)
            atomicAdd(&g_KS[bh * ND + ty * 4 + i], ksp[i]);
    }
}

// ---------------------------------------------------------------------------
// out[t,e] = q[t,e] + (sum_d q[t,d]*kv[d,e]) / (sum_d q[t,d]*ksum[d])
// One block per (32 tokens, b*h). 256 threads: e = tid&63, 4 token groups.
// ---------------------------------------------------------------------------
__global__ __launch_bounds__(256) void attn_kernel()
{
    const int bh = blockIdx.y;
    const int b = bh / NH, h = bh % NH;
    const int t0 = blockIdx.x * 32;

    __shared__ float kvs[ND][ND];
    __shared__ float kss[ND];
    __shared__ float qs[32][ND];

    const int tid = threadIdx.x;
    const float* kvp = g_KV + bh * ND * ND;
    #pragma unroll
    for (int i = 0; i < 4; i++) {
        int idx = i * 256 + tid;           // 1024 float4
        int row = idx >> 4, c4 = (idx & 15) << 2;
        *reinterpret_cast<float4*>(&kvs[row][c4]) =
            *reinterpret_cast<const float4*>(kvp + row * ND + c4);
    }
    if (tid < 16)
        *reinterpret_cast<float4*>(&kss[tid * 4]) =
            *reinterpret_cast<const float4*>(g_KS + bh * ND + tid * 4);

    const float* qp = g_Q + ((size_t)b * NT + t0) * NC + h * ND;
    #pragma unroll
    for (int i = 0; i < 2; i++) {
        int idx = i * 256 + tid;           // 512 float4
        int row = idx >> 4, c4 = (idx & 15) << 2;
        *reinterpret_cast<float4*>(&qs[row][c4]) =
            *reinterpret_cast<const float4*>(qp + (size_t)row * NC + c4);
    }
    __syncthreads();

    const int e = tid & 63, tg = tid >> 6;
    float* outp = g_A + ((size_t)b * NT + t0) * NC + h * ND;
    for (int tt = tg; tt < 32; tt += 4) {
        float ds = 0.f, os = 0.f;
        #pragma unroll
        for (int d = 0; d < ND; d++) {
            float qd = qs[tt][d];
            ds = fmaf(qd, kss[d], ds);
            os = fmaf(qd, kvs[d][e], os);
        }
        outp[(size_t)tt * NC + e] = qs[tt][e] + os / ds;
    }
}

// ---------------------------------------------------------------------------
extern "C" void kernel_launch(void* const* d_in, const int* in_sizes, int n_in,
                              void* d_out, int out_size)
{
    const float* x  = (const float*)d_in[0];
    const float* y  = (const float*)d_in[1];
    const float* Wq = (const float*)d_in[2];
    const float* bq = (const float*)d_in[3];
    const float* Wk = (const float*)d_in[4];
    const float* bk = (const float*)d_in[5];
    const float* Wv = (const float*)d_in[6];
    const float* bv = (const float*)d_in[7];
    const float* Wp = (const float*)d_in[8];
    const float* bp = (const float*)d_in[9];
    float* out = (float*)d_out;

    (void)in_sizes; (void)n_in; (void)out_size;

    // 1. Q/K/V projections (fused, grid.z selects GEMM)
    qkv_gemm_kernel<<<dim3(NC / 128, NM / 128, 3), 256>>>(x, y, Wq, bq, Wk, bk, Wv, bv);

    // 2. Per-head softmax on Q and K (grid.y selects tensor)
    softmax_kernel<<<dim3((NM * NH) / 8, 2), 256>>>();

    // 3. Zero KV/KS accumulators
    zero_kernel<<<(NB * NH * ND * ND + 255) / 256, 256>>>();

    // 4. kv = K^T V, ksum = sum_n K  (split over T, atomic accumulate)
    kv_kernel<<<dim3(NB * NH, KVSPLIT), 256>>>();

    // 5. Linear-attention combine -> g_A
    attn_kernel<<<dim3(NT / 32, NB * NH), 256>>>();

    // 6. Output projection -> d_out
    proj_gemm_kernel<<<dim3(NC / 128, NM / 128), 256>>>(Wp, bp, out);
}

// round 3
// speedup vs baseline: 1.8714x; 1.8714x over previous
#include <cuda_runtime.h>
#include <cuda_bf16.h>
#include <cstdint>

#define NB 4
#define NT 4096
#define NC 1024
#define NH 16
#define ND 64
#define NM (NB*NT)          // 16384 rows
#define KVSPLIT 8

// ---------------------------------------------------------------------------
// Device global scratch (allocation-free requirement)
// ---------------------------------------------------------------------------
__device__ __nv_bfloat16 g_xhi[(size_t)NM*NC], g_xlo[(size_t)NM*NC];
__device__ __nv_bfloat16 g_yhi[(size_t)NM*NC], g_ylo[(size_t)NM*NC];
__device__ __nv_bfloat16 g_ahi[(size_t)NM*NC], g_alo[(size_t)NM*NC];
__device__ __nv_bfloat16 g_wqhi[NC*NC], g_wqlo[NC*NC];
__device__ __nv_bfloat16 g_wkhi[NC*NC], g_wklo[NC*NC];
__device__ __nv_bfloat16 g_wvhi[NC*NC], g_wvlo[NC*NC];
__device__ __nv_bfloat16 g_wphi[NC*NC], g_wplo[NC*NC];
__device__ float g_Q[(size_t)NM*NC];
__device__ float g_K[(size_t)NM*NC];
__device__ float g_V[(size_t)NM*NC];
__device__ float g_KV[NB*NH*ND*ND];
__device__ float g_KS[NB*NH*ND];

// ---------------------------------------------------------------------------
// PTX helpers (sm_80+ portable: cp.async / ldmatrix / mma.sync)
// ---------------------------------------------------------------------------
__device__ __forceinline__ uint32_t smem_to_u32(const void* p) {
    uint32_t a;
    asm("{ .reg .u64 t; cvta.to.shared.u64 t, %1; cvt.u32.u64 %0, t; }" : "=r"(a) : "l"(p));
    return a;
}
__device__ __forceinline__ void cp16(uint32_t s, const void* g) {
    asm volatile("cp.async.cg.shared.global [%0], [%1], 16;" :: "r"(s), "l"(g));
}
__device__ __forceinline__ void cp_commit() { asm volatile("cp.async.commit_group;" ::: "memory"); }
template<int N> __device__ __forceinline__ void cp_wait() {
    asm volatile("cp.async.wait_group %0;" :: "n"(N) : "memory");
}
__device__ __forceinline__ void ldm_x4(uint32_t addr, uint32_t* r) {
    asm volatile("ldmatrix.sync.aligned.m8n8.x4.shared.b16 {%0,%1,%2,%3}, [%4];"
                 : "=r"(r[0]), "=r"(r[1]), "=r"(r[2]), "=r"(r[3]) : "r"(addr));
}
__device__ __forceinline__ void mma_bf16(float* d, const uint32_t* a, const uint32_t* b) {
    asm volatile("mma.sync.aligned.m16n8k16.row.col.f32.bf16.bf16.f32 "
                 "{%0,%1,%2,%3}, {%4,%5,%6,%7}, {%8,%9}, {%0,%1,%2,%3};"
                 : "+f"(d[0]), "+f"(d[1]), "+f"(d[2]), "+f"(d[3])
                 : "r"(a[0]), "r"(a[1]), "r"(a[2]), "r"(a[3]), "r"(b[0]), "r"(b[1]));
}

// softmax over 64 cols: 16 values per lane + quad reduction (xor 1, 2)
__device__ __forceinline__ void softmax16(float* v) {
    float mx = v[0];
    #pragma unroll
    for (int j = 1; j < 16; j++) mx = fmaxf(mx, v[j]);
    mx = fmaxf(mx, __shfl_xor_sync(0xffffffffu, mx, 1));
    mx = fmaxf(mx, __shfl_xor_sync(0xffffffffu, mx, 2));
    float s = 0.f;
    #pragma unroll
    for (int j = 0; j < 16; j++) { v[j] = __expf(v[j] - mx); s += v[j]; }
    s += __shfl_xor_sync(0xffffffffu, s, 1);
    s += __shfl_xor_sync(0xffffffffu, s, 2);
    float inv = 1.f / s;
    #pragma unroll
    for (int j = 0; j < 16; j++) v[j] *= inv;
}

// ---------------------------------------------------------------------------
// bf16x3 GEMM: Out[m,n] = sum_k A[m,k]*W[n,k] + bias[n], optional per-64 softmax.
// CTA 128x128, BK=32, 4-stage cp.async pipeline, 8 warps (32x64 each).
// Smem rows padded to 40 bf16 (80B) -> conflict-free ldmatrix/cp.async.
// ---------------------------------------------------------------------------
#define BM 128
#define BN 128
#define BK 32
#define STAGES 4
#define NKT (NC/BK)               // 32
#define SROW 40                   // padded row length in bf16
#define MAT_BYTES (128*SROW*2)    // 10240
#define STG_BYTES (4*MAT_BYTES)   // 40960
#define GSMEM (STAGES*STG_BYTES)  // 163840

__device__ __forceinline__ void gemm_body(
    const __nv_bfloat16* __restrict__ Ahi, const __nv_bfloat16* __restrict__ Alo,
    const __nv_bfloat16* __restrict__ Bhi, const __nv_bfloat16* __restrict__ Blo,
    const float* __restrict__ bias, float* __restrict__ Out, int do_softmax)
{
    extern __shared__ __align__(128) char sm[];
    uint32_t smb = smem_to_u32(sm);
    const int tid = threadIdx.x;
    const int m0 = blockIdx.y * BM, n0 = blockIdx.x * BN;

    const __nv_bfloat16* gbase[4] = {
        Ahi + (size_t)m0 * NC, Alo + (size_t)m0 * NC,
        Bhi + (size_t)n0 * NC, Blo + (size_t)n0 * NC };

    auto issue = [&](int stage, int k0) {
        uint32_t sb = smb + stage * STG_BYTES;
        #pragma unroll
        for (int i = 0; i < 8; i++) {
            int g = i * 256 + tid;
            int mat = g >> 9, w = g & 511, row = w >> 2, c = w & 3;
            uint32_t sa = sb + mat * MAT_BYTES + row * (SROW * 2) + c * 16;
            cp16(sa, gbase[mat] + (size_t)row * NC + k0 + c * 8);
        }
    };

    #pragma unroll
    for (int s = 0; s < STAGES - 1; s++) { issue(s, s * BK); cp_commit(); }

    const int wid = tid >> 5, lane = tid & 31;
    const int wm = wid & 3, wn = wid >> 2;       // warp tile: 32(M) x 64(N)

    float acc[2][8][4];
    #pragma unroll
    for (int a = 0; a < 2; a++)
        #pragma unroll
        for (int b = 0; b < 8; b++)
            #pragma unroll
            for (int c = 0; c < 4; c++) acc[a][b][c] = 0.f;

    // ldmatrix address components
    const int a_row = wm * 32 + (lane & 7) + ((lane >> 3) & 1) * 8;   // + mt*16
    const int b_row = wn * 64 + (lane & 15);                           // + p*16
    const int colb  = (lane >> 4) * 16;                                // byte offset, + ks*32

    for (int kt = 0; kt < NKT; kt++) {
        cp_wait<STAGES - 2>();
        __syncthreads();
        uint32_t sb = smb + (kt % STAGES) * STG_BYTES;
        #pragma unroll
        for (int ks = 0; ks < 2; ks++) {
            uint32_t ah[2][4], al[2][4];
            #pragma unroll
            for (int mt = 0; mt < 2; mt++) {
                uint32_t ra = sb + (a_row + mt * 16) * (SROW * 2) + ks * 32 + colb;
                ldm_x4(ra, ah[mt]);
                ldm_x4(ra + MAT_BYTES, al[mt]);
            }
            uint32_t bh[8][2], bl[8][2];
            #pragma unroll
            for (int p = 0; p < 4; p++) {
                uint32_t rb = sb + 2 * MAT_BYTES + (b_row + p * 16) * (SROW * 2) + ks * 32 + colb;
                uint32_t t[4];
                ldm_x4(rb, t);
                bh[2*p][0] = t[0]; bh[2*p+1][0] = t[1]; bh[2*p][1] = t[2]; bh[2*p+1][1] = t[3];
                ldm_x4(rb + MAT_BYTES, t);
                bl[2*p][0] = t[0]; bl[2*p+1][0] = t[1]; bl[2*p][1] = t[2]; bl[2*p+1][1] = t[3];
            }
            #pragma unroll
            for (int mt = 0; mt < 2; mt++)
                #pragma unroll
                for (int nt = 0; nt < 8; nt++) {
                    mma_bf16(acc[mt][nt], ah[mt], bh[nt]);
                    mma_bf16(acc[mt][nt], ah[mt], bl[nt]);
                    mma_bf16(acc[mt][nt], al[mt], bh[nt]);
                }
        }
        __syncthreads();
        if (kt + STAGES - 1 < NKT) issue((kt + STAGES - 1) % STAGES, (kt + STAGES - 1) * BK);
        cp_commit();
    }

    // ---- Epilogue: bias (+softmax per 64-wide head) + store ----
    float2 bias2[8];
    const int cb = n0 + wn * 64 + (lane & 3) * 2;
    #pragma unroll
    for (int nt = 0; nt < 8; nt++)
        bias2[nt] = *reinterpret_cast<const float2*>(&bias[cb + nt * 8]);

    #pragma unroll
    for (int mt = 0; mt < 2; mt++) {
        float va[16], vb[16];
        #pragma unroll
        for (int nt = 0; nt < 8; nt++) {
            va[2*nt]   = acc[mt][nt][0] + bias2[nt].x;
            va[2*nt+1] = acc[mt][nt][1] + bias2[nt].y;
            vb[2*nt]   = acc[mt][nt][2] + bias2[nt].x;
            vb[2*nt+1] = acc[mt][nt][3] + bias2[nt].y;
        }
        if (do_softmax) { softmax16(va); softmax16(vb); }
        const int rowa = m0 + wm * 32 + mt * 16 + (lane >> 2);
        const int rowb = rowa + 8;
        #pragma unroll
        for (int nt = 0; nt < 8; nt++) {
            *reinterpret_cast<float2*>(&Out[(size_t)rowa * NC + cb + nt * 8]) =
                make_float2(va[2*nt], va[2*nt+1]);
            *reinterpret_cast<float2*>(&Out[(size_t)rowb * NC + cb + nt * 8]) =
                make_float2(vb[2*nt], vb[2*nt+1]);
        }
    }
}

__global__ __launch_bounds__(256, 1) void qkv_gemm(
    const float* __restrict__ bq, const float* __restrict__ bk, const float* __restrict__ bv)
{
    int z = blockIdx.z;
    if (z == 0)      gemm_body(g_xhi, g_xlo, g_wqhi, g_wqlo, bq, g_Q, 1);
    else if (z == 1) gemm_body(g_yhi, g_ylo, g_wkhi, g_wklo, bk, g_K, 1);
    else             gemm_body(g_yhi, g_ylo, g_wvhi, g_wvlo, bv, g_V, 0);
}

__global__ __launch_bounds__(256, 1) void proj_gemm(
    const float* __restrict__ bp, float* __restrict__ out)
{
    gemm_body(g_ahi, g_alo, g_wphi, g_wplo, bp, out, 0);
}

// ---------------------------------------------------------------------------
// fp32 -> hi/lo bf16 split (row-major, same layout as source)
// ---------------------------------------------------------------------------
__global__ __launch_bounds__(256) void convert_hilo(const float* __restrict__ src, int mode)
{
    __nv_bfloat16 *dh, *dl; int n8;
    switch (mode) {
        case 0: dh = g_xhi;  dl = g_xlo;  n8 = NM * NC / 8; break;
        case 1: dh = g_yhi;  dl = g_ylo;  n8 = NM * NC / 8; break;
        case 2: dh = g_wqhi; dl = g_wqlo; n8 = NC * NC / 8; break;
        case 3: dh = g_wkhi; dl = g_wklo; n8 = NC * NC / 8; break;
        case 4: dh = g_wvhi; dl = g_wvlo; n8 = NC * NC / 8; break;
        default: dh = g_wphi; dl = g_wplo; n8 = NC * NC / 8; break;
    }
    int g = blockIdx.x * 256 + threadIdx.x;
    if (g >= n8) return;
    const float4* p = reinterpret_cast<const float4*>(src) + g * 2;
    float4 a = p[0], b = p[1];
    float vs[8] = {a.x, a.y, a.z, a.w, b.x, b.y, b.z, b.w};
    alignas(16) __nv_bfloat16 hi[8], lo[8];
    #pragma unroll
    for (int j = 0; j < 8; j++) {
        hi[j] = __float2bfloat16(vs[j]);
        lo[j] = __float2bfloat16(vs[j] - __bfloat162float(hi[j]));
    }
    *reinterpret_cast<uint4*>(dh + (size_t)g * 8) = *reinterpret_cast<uint4*>(hi);
    *reinterpret_cast<uint4*>(dl + (size_t)g * 8) = *reinterpret_cast<uint4*>(lo);
}

// ---------------------------------------------------------------------------
__global__ void zero_kernel()
{
    int i = blockIdx.x * blockDim.x + threadIdx.x;
    if (i < NB * NH * ND * ND) g_KV[i] = 0.f;
    if (i < NB * NH * ND)      g_KS[i] = 0.f;
}

// kv[d][e] = sum_n K[n,d]*V[n,e]; ksum[d] = sum_n K[n,d]
__global__ __launch_bounds__(256) void kv_kernel()
{
    const int bh    = blockIdx.x;
    const int split = blockIdx.y;
    const float* Kp = g_K + (size_t)(bh / NH) * NT * NC + (bh % NH) * ND;
    const float* Vp = g_V + (size_t)(bh / NH) * NT * NC + (bh % NH) * ND;

    __shared__ float Ks[32][ND];
    __shared__ float Vs[32][ND];

    const int tid = threadIdx.x;
    const int ty = tid >> 4, tx = tid & 15;

    float acc[4][4] = {};
    float ksp[4]    = {};

    const int nbase = split * (NT / KVSPLIT);
    for (int it = 0; it < (NT / KVSPLIT) / 32; it++) {
        int n0 = nbase + it * 32;
        #pragma unroll
        for (int i = 0; i < 2; i++) {
            int idx = i * 256 + tid;
            int rw = idx >> 4;
            int c4 = (idx & 15) << 2;
            *reinterpret_cast<float4*>(&Ks[rw][c4]) =
                *reinterpret_cast<const float4*>(Kp + (size_t)(n0 + rw) * NC + c4);
            *reinterpret_cast<float4*>(&Vs[rw][c4]) =
                *reinterpret_cast<const float4*>(Vp + (size_t)(n0 + rw) * NC + c4);
        }
        __syncthreads();
        #pragma unroll 8
        for (int n = 0; n < 32; n++) {
            float ra[4], rb[4];
            #pragma unroll
            for (int i = 0; i < 4; i++) ra[i] = Ks[n][ty * 4 + i];
            #pragma unroll
            for (int j = 0; j < 4; j++) rb[j] = Vs[n][tx * 4 + j];
            #pragma unroll
            for (int i = 0; i < 4; i++)
                #pragma unroll
                for (int j = 0; j < 4; j++)
                    acc[i][j] = fmaf(ra[i], rb[j], acc[i][j]);
            if (tx == 0) {
                #pragma unroll
                for (int i = 0; i < 4; i++) ksp[i] += ra[i];
            }
        }
        __syncthreads();
    }

    float* kvout = g_KV + bh * ND * ND;
    #pragma unroll
    for (int i = 0; i < 4; i++)
        #pragma unroll
        for (int j = 0; j < 4; j++)
            atomicAdd(&kvout[(ty * 4 + i) * ND + tx * 4 + j], acc[i][j]);
    if (tx == 0) {
        #pragma unroll
        for (int i = 0; i < 4; i++)
            atomicAdd(&g_KS[bh * ND + ty * 4 + i], ksp[i]);
    }
}

// out[t,e] = q[t,e] + (sum_d q[t,d]*kv[d,e]) / (sum_d q[t,d]*ksum[d])
// -> writes hi/lo bf16 row-major for the proj GEMM
__global__ __launch_bounds__(256) void attn_kernel()
{
    const int bh = blockIdx.y;
    const int b = bh / NH, h = bh % NH;
    const int t0 = blockIdx.x * 32;

    __shared__ float kvs[ND][ND];
    __shared__ float kss[ND];
    __shared__ float qs[32][ND];

    const int tid = threadIdx.x;
    const float* kvp = g_KV + bh * ND * ND;
    #pragma unroll
    for (int i = 0; i < 4; i++) {
        int idx = i * 256 + tid;
        int rw = idx >> 4, c4 = (idx & 15) << 2;
        *reinterpret_cast<float4*>(&kvs[rw][c4]) =
            *reinterpret_cast<const float4*>(kvp + rw * ND + c4);
    }
    if (tid < 16)
        *reinterpret_cast<float4*>(&kss[tid * 4]) =
            *reinterpret_cast<const float4*>(g_KS + bh * ND + tid * 4);

    const float* qp = g_Q + ((size_t)b * NT + t0) * NC + h * ND;
    #pragma unroll
    for (int i = 0; i < 2; i++) {
        int idx = i * 256 + tid;
        int rw = idx >> 4, c4 = (idx & 15) << 2;
        *reinterpret_cast<float4*>(&qs[rw][c4]) =
            *reinterpret_cast<const float4*>(qp + (size_t)rw * NC + c4);
    }
    __syncthreads();

    const int e = tid & 63, tg = tid >> 6;
    for (int tt = tg; tt < 32; tt += 4) {
        float ds = 0.f, os = 0.f;
        #pragma unroll
        for (int d = 0; d < ND; d++) {
            float qd = qs[tt][d];
            ds = fmaf(qd, kss[d], ds);
            os = fmaf(qd, kvs[d][e], os);
        }
        float val = qs[tt][e] + os / ds;
        size_t idx = ((size_t)b * NT + t0 + tt) * NC + h * ND + e;
        __nv_bfloat16 hi = __float2bfloat16(val);
        g_ahi[idx] = hi;
        g_alo[idx] = __float2bfloat16(val - __bfloat162float(hi));
    }
}

// ---------------------------------------------------------------------------
extern "C" void kernel_launch(void* const* d_in, const int* in_sizes, int n_in,
                              void* d_out, int out_size)
{
    const float* x  = (const float*)d_in[0];
    const float* y  = (const float*)d_in[1];
    const float* Wq = (const float*)d_in[2];
    const float* bq = (const float*)d_in[3];
    const float* Wk = (const float*)d_in[4];
    const float* bk = (const float*)d_in[5];
    const float* Wv = (const float*)d_in[6];
    const float* bv = (const float*)d_in[7];
    const float* Wp = (const float*)d_in[8];
    const float* bp = (const float*)d_in[9];
    float* out = (float*)d_out;
    (void)in_sizes; (void)n_in; (void)out_size;

    cudaFuncSetAttribute(qkv_gemm,  cudaFuncAttributeMaxDynamicSharedMemorySize, GSMEM);
    cudaFuncSetAttribute(proj_gemm, cudaFuncAttributeMaxDynamicSharedMemorySize, GSMEM);

    // 1. fp32 -> hi/lo bf16 splits
    int actg = (NM * NC / 8 + 255) / 256;
    int wg   = (NC * NC / 8 + 255) / 256;
    convert_hilo<<<actg, 256>>>(x, 0);
    convert_hilo<<<actg, 256>>>(y, 1);
    convert_hilo<<<wg, 256>>>(Wq, 2);
    convert_hilo<<<wg, 256>>>(Wk, 3);
    convert_hilo<<<wg, 256>>>(Wv, 4);
    convert_hilo<<<wg, 256>>>(Wp, 5);

    // 2. Q/K/V projections (softmax fused for Q,K)
    qkv_gemm<<<dim3(NC / BN, NM / BM, 3), 256, GSMEM>>>(bq, bk, bv);

    // 3. kv = K^T V, ksum = sum K
    zero_kernel<<<(NB * NH * ND * ND + 255) / 256, 256>>>();
    kv_kernel<<<dim3(NB * NH, KVSPLIT), 256>>>();

    // 4. linear-attention combine -> hi/lo bf16 for proj GEMM
    attn_kernel<<<dim3(NT / 32, NB * NH), 256>>>();

    // 5. output projection -> d_out
    proj_gemm<<<dim3(NC / BN, NM / BM, 1), 256, GSMEM>>>(bp, out);
}

// round 4
// speedup vs baseline: 1.9128x; 1.0222x over previous
#include <cuda_runtime.h>
#include <cuda_bf16.h>
#include <cstdint>

#define NB 4
#define NT 4096
#define NC 1024
#define NH 16
#define ND 64
#define NM (NB*NT)          // 16384 rows
#define KVSPLIT 8

// ---------------------------------------------------------------------------
// Device global scratch (allocation-free requirement)
// ---------------------------------------------------------------------------
__device__ __nv_bfloat16 g_xhi[(size_t)NM*NC], g_xlo[(size_t)NM*NC];
__device__ __nv_bfloat16 g_yhi[(size_t)NM*NC], g_ylo[(size_t)NM*NC];
__device__ __nv_bfloat16 g_ahi[(size_t)NM*NC], g_alo[(size_t)NM*NC];
__device__ __nv_bfloat16 g_wqhi[NC*NC], g_wqlo[NC*NC];
__device__ __nv_bfloat16 g_wkhi[NC*NC], g_wklo[NC*NC];
__device__ __nv_bfloat16 g_wvhi[NC*NC], g_wvlo[NC*NC];
__device__ __nv_bfloat16 g_wphi[NC*NC], g_wplo[NC*NC];
__device__ float g_Q[(size_t)NM*NC];
__device__ float g_K[(size_t)NM*NC];
__device__ float g_V[(size_t)NM*NC];
__device__ float g_KV[NB*NH*ND*ND];
__device__ float g_KS[NB*NH*ND];

// ---------------------------------------------------------------------------
// PTX helpers (sm_80+ portable: cp.async / ldmatrix / mma.sync)
// ---------------------------------------------------------------------------
__device__ __forceinline__ uint32_t smem_to_u32(const void* p) {
    uint32_t a;
    asm("{ .reg .u64 t; cvta.to.shared.u64 t, %1; cvt.u32.u64 %0, t; }" : "=r"(a) : "l"(p));
    return a;
}
__device__ __forceinline__ void cp16(uint32_t s, const void* g) {
    asm volatile("cp.async.cg.shared.global [%0], [%1], 16;" :: "r"(s), "l"(g));
}
__device__ __forceinline__ void cp_commit() { asm volatile("cp.async.commit_group;" ::: "memory"); }
template<int N> __device__ __forceinline__ void cp_wait() {
    asm volatile("cp.async.wait_group %0;" :: "n"(N) : "memory");
}
__device__ __forceinline__ void ldm_x4(uint32_t addr, uint32_t* r) {
    asm volatile("ldmatrix.sync.aligned.m8n8.x4.shared.b16 {%0,%1,%2,%3}, [%4];"
                 : "=r"(r[0]), "=r"(r[1]), "=r"(r[2]), "=r"(r[3]) : "r"(addr));
}
__device__ __forceinline__ void mma_bf16(float* d, const uint32_t* a, const uint32_t* b) {
    asm volatile("mma.sync.aligned.m16n8k16.row.col.f32.bf16.bf16.f32 "
                 "{%0,%1,%2,%3}, {%4,%5,%6,%7}, {%8,%9}, {%0,%1,%2,%3};"
                 : "+f"(d[0]), "+f"(d[1]), "+f"(d[2]), "+f"(d[3])
                 : "r"(a[0]), "r"(a[1]), "r"(a[2]), "r"(a[3]), "r"(b[0]), "r"(b[1]));
}

// softmax over 64 cols: 16 values per lane + quad reduction (xor 1, 2)
__device__ __forceinline__ void softmax16(float* v) {
    float mx = v[0];
    #pragma unroll
    for (int j = 1; j < 16; j++) mx = fmaxf(mx, v[j]);
    mx = fmaxf(mx, __shfl_xor_sync(0xffffffffu, mx, 1));
    mx = fmaxf(mx, __shfl_xor_sync(0xffffffffu, mx, 2));
    float s = 0.f;
    #pragma unroll
    for (int j = 0; j < 16; j++) { v[j] = __expf(v[j] - mx); s += v[j]; }
    s += __shfl_xor_sync(0xffffffffu, s, 1);
    s += __shfl_xor_sync(0xffffffffu, s, 2);
    float inv = 1.f / s;
    #pragma unroll
    for (int j = 0; j < 16; j++) v[j] *= inv;
}

// ---------------------------------------------------------------------------
// bf16x3 GEMM: Out[m,n] = sum_k A[m,k]*W[n,k] + bias[n], optional per-64 softmax.
// CTA 128(M) x 256(N), BK=32, 3-stage cp.async pipeline.
// 8 warps as 2(M) x 4(N); warp tile 64x64 -> 16 LDSM.x4 : 96 MMA per ks.
// Smem rows padded to 40 bf16 (80B) -> conflict-free ldmatrix/cp.async.
// ---------------------------------------------------------------------------
#define BM 128
#define BN 256
#define BK 32
#define STAGES 3
#define NKT (NC/BK)                // 32
#define SROW 40                    // padded row length in bf16
#define AMAT (128*SROW*2)          // 10240 bytes per A matrix (hi or lo)
#define BMAT (256*SROW*2)          // 20480 bytes per B matrix
#define OFF_BHI (2*AMAT)           // 20480
#define OFF_BLO (OFF_BHI + BMAT)   // 40960
#define STG_BYTES (2*AMAT + 2*BMAT) // 61440
#define GSMEM (STAGES*STG_BYTES)    // 184320

__device__ __forceinline__ void gemm_body(
    const __nv_bfloat16* __restrict__ Ahi, const __nv_bfloat16* __restrict__ Alo,
    const __nv_bfloat16* __restrict__ Bhi, const __nv_bfloat16* __restrict__ Blo,
    const float* __restrict__ bias, float* __restrict__ Out, int do_softmax)
{
    extern __shared__ __align__(128) char sm[];
    uint32_t smb = smem_to_u32(sm);
    const int tid = threadIdx.x;
    const int m0 = blockIdx.y * BM, n0 = blockIdx.x * BN;

    const __nv_bfloat16* a_hi = Ahi + (size_t)m0 * NC;
    const __nv_bfloat16* a_lo = Alo + (size_t)m0 * NC;
    const __nv_bfloat16* b_hi = Bhi + (size_t)n0 * NC;
    const __nv_bfloat16* b_lo = Blo + (size_t)n0 * NC;

    auto issue = [&](int stage, int k0) {
        uint32_t sb = smb + stage * STG_BYTES;
        #pragma unroll
        for (int i = 0; i < 2; i++) {                 // A hi/lo: 512 cp16 each
            int g = i * 256 + tid;
            int row = g >> 2, c = g & 3;
            uint32_t so = row * (SROW * 2) + c * 16;
            size_t  go = (size_t)row * NC + k0 + c * 8;
            cp16(sb + so,        a_hi + go);
            cp16(sb + AMAT + so, a_lo + go);
        }
        #pragma unroll
        for (int i = 0; i < 4; i++) {                 // B hi/lo: 1024 cp16 each
            int g = i * 256 + tid;
            int row = g >> 2, c = g & 3;
            uint32_t so = row * (SROW * 2) + c * 16;
            size_t  go = (size_t)row * NC + k0 + c * 8;
            cp16(sb + OFF_BHI + so, b_hi + go);
            cp16(sb + OFF_BLO + so, b_lo + go);
        }
    };

    #pragma unroll
    for (int s = 0; s < STAGES - 1; s++) { issue(s, s * BK); cp_commit(); }

    const int wid = tid >> 5, lane = tid & 31;
    const int wm = wid & 1, wn = wid >> 1;            // warp tile: 64(M) x 64(N)

    float acc[4][8][4];
    #pragma unroll
    for (int a = 0; a < 4; a++)
        #pragma unroll
        for (int b = 0; b < 8; b++)
            #pragma unroll
            for (int c = 0; c < 4; c++) acc[a][b][c] = 0.f;

    // ldmatrix address components
    const int a_row = wm * 64 + (lane & 7) + ((lane >> 3) & 1) * 8;   // + mt*16
    const int b_row = wn * 64 + (lane & 15);                           // + p*16
    const int colb  = (lane >> 4) * 16;                                // byte offset, + ks*32

    for (int kt = 0; kt < NKT; kt++) {
        cp_wait<STAGES - 2>();
        __syncthreads();
        uint32_t sb = smb + (kt % STAGES) * STG_BYTES;
        #pragma unroll
        for (int ks = 0; ks < 2; ks++) {
            uint32_t ah[4][4], al[4][4];
            #pragma unroll
            for (int mt = 0; mt < 4; mt++) {
                uint32_t ra = sb + (a_row + mt * 16) * (SROW * 2) + ks * 32 + colb;
                ldm_x4(ra, ah[mt]);
                ldm_x4(ra + AMAT, al[mt]);
            }
            uint32_t bh[8][2], bl[8][2];
            #pragma unroll
            for (int p = 0; p < 4; p++) {
                uint32_t rb = sb + OFF_BHI + (b_row + p * 16) * (SROW * 2) + ks * 32 + colb;
                uint32_t t[4];
                ldm_x4(rb, t);
                bh[2*p][0] = t[0]; bh[2*p+1][0] = t[1]; bh[2*p][1] = t[2]; bh[2*p+1][1] = t[3];
                ldm_x4(rb + BMAT, t);
                bl[2*p][0] = t[0]; bl[2*p+1][0] = t[1]; bl[2*p][1] = t[2]; bl[2*p+1][1] = t[3];
            }
            // three passes separated -> accumulator RAW distance = 32 MMAs
            #pragma unroll
            for (int mt = 0; mt < 4; mt++)
                #pragma unroll
                for (int nt = 0; nt < 8; nt++) mma_bf16(acc[mt][nt], ah[mt], bh[nt]);
            #pragma unroll
            for (int mt = 0; mt < 4; mt++)
                #pragma unroll
                for (int nt = 0; nt < 8; nt++) mma_bf16(acc[mt][nt], ah[mt], bl[nt]);
            #pragma unroll
            for (int mt = 0; mt < 4; mt++)
                #pragma unroll
                for (int nt = 0; nt < 8; nt++) mma_bf16(acc[mt][nt], al[mt], bh[nt]);
        }
        __syncthreads();
        if (kt + STAGES - 1 < NKT) issue((kt + STAGES - 1) % STAGES, (kt + STAGES - 1) * BK);
        cp_commit();
    }

    // ---- Epilogue: bias (+softmax per 64-wide head) + store ----
    float2 bias2[8];
    const int cb = n0 + wn * 64 + (lane & 3) * 2;
    #pragma unroll
    for (int nt = 0; nt < 8; nt++)
        bias2[nt] = *reinterpret_cast<const float2*>(&bias[cb + nt * 8]);

    #pragma unroll
    for (int mt = 0; mt < 4; mt++) {
        float va[16], vb[16];
        #pragma unroll
        for (int nt = 0; nt < 8; nt++) {
            va[2*nt]   = acc[mt][nt][0] + bias2[nt].x;
            va[2*nt+1] = acc[mt][nt][1] + bias2[nt].y;
            vb[2*nt]   = acc[mt][nt][2] + bias2[nt].x;
            vb[2*nt+1] = acc[mt][nt][3] + bias2[nt].y;
        }
        if (do_softmax) { softmax16(va); softmax16(vb); }
        const int rowa = m0 + wm * 64 + mt * 16 + (lane >> 2);
        const int rowb = rowa + 8;
        #pragma unroll
        for (int nt = 0; nt < 8; nt++) {
            *reinterpret_cast<float2*>(&Out[(size_t)rowa * NC + cb + nt * 8]) =
                make_float2(va[2*nt], va[2*nt+1]);
            *reinterpret_cast<float2*>(&Out[(size_t)rowb * NC + cb + nt * 8]) =
                make_float2(vb[2*nt], vb[2*nt+1]);
        }
    }
}

__global__ __launch_bounds__(256, 1) void qkv_gemm(
    const float* __restrict__ bq, const float* __restrict__ bk, const float* __restrict__ bv)
{
    int z = blockIdx.z;
    if (z == 0)      gemm_body(g_xhi, g_xlo, g_wqhi, g_wqlo, bq, g_Q, 1);
    else if (z == 1) gemm_body(g_yhi, g_ylo, g_wkhi, g_wklo, bk, g_K, 1);
    else             gemm_body(g_yhi, g_ylo, g_wvhi, g_wvlo, bv, g_V, 0);
}

__global__ __launch_bounds__(256, 1) void proj_gemm(
    const float* __restrict__ bp, float* __restrict__ out)
{
    gemm_body(g_ahi, g_alo, g_wphi, g_wplo, bp, out, 0);
}

// ---------------------------------------------------------------------------
// fp32 -> hi/lo bf16 split (row-major, same layout as source)
// ---------------------------------------------------------------------------
__global__ __launch_bounds__(256) void convert_hilo(const float* __restrict__ src, int mode)
{
    __nv_bfloat16 *dh, *dl; int n8;
    switch (mode) {
        case 0: dh = g_xhi;  dl = g_xlo;  n8 = NM * NC / 8; break;
        case 1: dh = g_yhi;  dl = g_ylo;  n8 = NM * NC / 8; break;
        case 2: dh = g_wqhi; dl = g_wqlo; n8 = NC * NC / 8; break;
        case 3: dh = g_wkhi; dl = g_wklo; n8 = NC * NC / 8; break;
        case 4: dh = g_wvhi; dl = g_wvlo; n8 = NC * NC / 8; break;
        default: dh = g_wphi; dl = g_wplo; n8 = NC * NC / 8; break;
    }
    int g = blockIdx.x * 256 + threadIdx.x;
    if (g >= n8) return;
    const float4* p = reinterpret_cast<const float4*>(src) + g * 2;
    float4 a = p[0], b = p[1];
    float vs[8] = {a.x, a.y, a.z, a.w, b.x, b.y, b.z, b.w};
    alignas(16) __nv_bfloat16 hi[8], lo[8];
    #pragma unroll
    for (int j = 0; j < 8; j++) {
        hi[j] = __float2bfloat16(vs[j]);
        lo[j] = __float2bfloat16(vs[j] - __bfloat162float(hi[j]));
    }
    *reinterpret_cast<uint4*>(dh + (size_t)g * 8) = *reinterpret_cast<uint4*>(hi);
    *reinterpret_cast<uint4*>(dl + (size_t)g * 8) = *reinterpret_cast<uint4*>(lo);
}

// ---------------------------------------------------------------------------
__global__ void zero_kernel()
{
    int i = blockIdx.x * blockDim.x + threadIdx.x;
    if (i < NB * NH * ND * ND) g_KV[i] = 0.f;
    if (i < NB * NH * ND)      g_KS[i] = 0.f;
}

// kv[d][e] = sum_n K[n,d]*V[n,e]; ksum[d] = sum_n K[n,d]
__global__ __launch_bounds__(256) void kv_kernel()
{
    const int bh    = blockIdx.x;
    const int split = blockIdx.y;
    const float* Kp = g_K + (size_t)(bh / NH) * NT * NC + (bh % NH) * ND;
    const float* Vp = g_V + (size_t)(bh / NH) * NT * NC + (bh % NH) * ND;

    __shared__ float Ks[32][ND];
    __shared__ float Vs[32][ND];

    const int tid = threadIdx.x;
    const int ty = tid >> 4, tx = tid & 15;

    float acc[4][4] = {};
    float ksp[4]    = {};

    const int nbase = split * (NT / KVSPLIT);
    for (int it = 0; it < (NT / KVSPLIT) / 32; it++) {
        int n0 = nbase + it * 32;
        #pragma unroll
        for (int i = 0; i < 2; i++) {
            int idx = i * 256 + tid;
            int rw = idx >> 4;
            int c4 = (idx & 15) << 2;
            *reinterpret_cast<float4*>(&Ks[rw][c4]) =
                *reinterpret_cast<const float4*>(Kp + (size_t)(n0 + rw) * NC + c4);
            *reinterpret_cast<float4*>(&Vs[rw][c4]) =
                *reinterpret_cast<const float4*>(Vp + (size_t)(n0 + rw) * NC + c4);
        }
        __syncthreads();
        #pragma unroll 8
        for (int n = 0; n < 32; n++) {
            float ra[4], rb[4];
            #pragma unroll
            for (int i = 0; i < 4; i++) ra[i] = Ks[n][ty * 4 + i];
            #pragma unroll
            for (int j = 0; j < 4; j++) rb[j] = Vs[n][tx * 4 + j];
            #pragma unroll
            for (int i = 0; i < 4; i++)
                #pragma unroll
                for (int j = 0; j < 4; j++)
                    acc[i][j] = fmaf(ra[i], rb[j], acc[i][j]);
            if (tx == 0) {
                #pragma unroll
                for (int i = 0; i < 4; i++) ksp[i] += ra[i];
            }
        }
        __syncthreads();
    }

    float* kvout = g_KV + bh * ND * ND;
    #pragma unroll
    for (int i = 0; i < 4; i++)
        #pragma unroll
        for (int j = 0; j < 4; j++)
            atomicAdd(&kvout[(ty * 4 + i) * ND + tx * 4 + j], acc[i][j]);
    if (tx == 0) {
        #pragma unroll
        for (int i = 0; i < 4; i++)
            atomicAdd(&g_KS[bh * ND + ty * 4 + i], ksp[i]);
    }
}

// out[t,e] = q[t,e] + (sum_d q[t,d]*kv[d,e]) / (sum_d q[t,d]*ksum[d])
// -> writes hi/lo bf16 row-major for the proj GEMM
__global__ __launch_bounds__(256) void attn_kernel()
{
    const int bh = blockIdx.y;
    const int b = bh / NH, h = bh % NH;
    const int t0 = blockIdx.x * 32;

    __shared__ float kvs[ND][ND];
    __shared__ float kss[ND];
    __shared__ float qs[32][ND];

    const int tid = threadIdx.x;
    const float* kvp = g_KV + bh * ND * ND;
    #pragma unroll
    for (int i = 0; i < 4; i++) {
        int idx = i * 256 + tid;
        int rw = idx >> 4, c4 = (idx & 15) << 2;
        *reinterpret_cast<float4*>(&kvs[rw][c4]) =
            *reinterpret_cast<const float4*>(kvp + rw * ND + c4);
    }
    if (tid < 16)
        *reinterpret_cast<float4*>(&kss[tid * 4]) =
            *reinterpret_cast<const float4*>(g_KS + bh * ND + tid * 4);

    const float* qp = g_Q + ((size_t)b * NT + t0) * NC + h * ND;
    #pragma unroll
    for (int i = 0; i < 2; i++) {
        int idx = i * 256 + tid;
        int rw = idx >> 4, c4 = (idx & 15) << 2;
        *reinterpret_cast<float4*>(&qs[rw][c4]) =
            *reinterpret_cast<const float4*>(qp + (size_t)rw * NC + c4);
    }
    __syncthreads();

    const int e = tid & 63, tg = tid >> 6;
    for (int tt = tg; tt < 32; tt += 4) {
        float ds = 0.f, os = 0.f;
        #pragma unroll
        for (int d = 0; d < ND; d++) {
            float qd = qs[tt][d];
            ds = fmaf(qd, kss[d], ds);
            os = fmaf(qd, kvs[d][e], os);
        }
        float val = qs[tt][e] + os / ds;
        size_t idx = ((size_t)b * NT + t0 + tt) * NC + h * ND + e;
        __nv_bfloat16 hi = __float2bfloat16(val);
        g_ahi[idx] = hi;
        g_alo[idx] = __float2bfloat16(val - __bfloat162float(hi));
    }
}

// ---------------------------------------------------------------------------
extern "C" void kernel_launch(void* const* d_in, const int* in_sizes, int n_in,
                              void* d_out, int out_size)
{
    const float* x  = (const float*)d_in[0];
    const float* y  = (const float*)d_in[1];
    const float* Wq = (const float*)d_in[2];
    const float* bq = (const float*)d_in[3];
    const float* Wk = (const float*)d_in[4];
    const float* bk = (const float*)d_in[5];
    const float* Wv = (const float*)d_in[6];
    const float* bv = (const float*)d_in[7];
    const float* Wp = (const float*)d_in[8];
    const float* bp = (const float*)d_in[9];
    float* out = (float*)d_out;
    (void)in_sizes; (void)n_in; (void)out_size;

    cudaFuncSetAttribute(qkv_gemm,  cudaFuncAttributeMaxDynamicSharedMemorySize, GSMEM);
    cudaFuncSetAttribute(proj_gemm, cudaFuncAttributeMaxDynamicSharedMemorySize, GSMEM);

    // 1. fp32 -> hi/lo bf16 splits
    int actg = (NM * NC / 8 + 255) / 256;
    int wg   = (NC * NC / 8 + 255) / 256;
    convert_hilo<<<actg, 256>>>(x, 0);
    convert_hilo<<<actg, 256>>>(y, 1);
    convert_hilo<<<wg, 256>>>(Wq, 2);
    convert_hilo<<<wg, 256>>>(Wk, 3);
    convert_hilo<<<wg, 256>>>(Wv, 4);
    convert_hilo<<<wg, 256>>>(Wp, 5);

    // 2. Q/K/V projections (softmax fused for Q,K)
    qkv_gemm<<<dim3(NC / BN, NM / BM, 3), 256, GSMEM>>>(bq, bk, bv);

    // 3. kv = K^T V, ksum = sum K
    zero_kernel<<<(NB * NH * ND * ND + 255) / 256, 256>>>();
    kv_kernel<<<dim3(NB * NH, KVSPLIT), 256>>>();

    // 4. linear-attention combine -> hi/lo bf16 for proj GEMM
    attn_kernel<<<dim3(NT / 32, NB * NH), 256>>>();

    // 5. output projection -> d_out
    proj_gemm<<<dim3(NC / BN, NM / BM, 1), 256, GSMEM>>>(bp, out);
}

// round 5
// speedup vs baseline: 2.5954x; 1.3568x over previous
#include <cuda_runtime.h>
#include <cuda_fp16.h>
#include <cstdint>

#define NB 4
#define NT 4096
#define NC 1024
#define NH 16
#define ND 64
#define NM (NB*NT)          // 16384 rows
#define KVSPLIT 8

// ---------------------------------------------------------------------------
// Device global scratch (allocation-free requirement)
// ---------------------------------------------------------------------------
__device__ __half g_xhi[(size_t)NM*NC], g_xlo[(size_t)NM*NC];
__device__ __half g_yhi[(size_t)NM*NC], g_ylo[(size_t)NM*NC];
__device__ __half g_ahi[(size_t)NM*NC], g_alo[(size_t)NM*NC];
__device__ __half g_wq[NC*NC];
__device__ __half g_wk[NC*NC];
__device__ __half g_wv[NC*NC];
__device__ __half g_wp[NC*NC];
__device__ float g_Q[(size_t)NM*NC];
__device__ float g_K[(size_t)NM*NC];
__device__ float g_V[(size_t)NM*NC];
__device__ float g_KV[NB*NH*ND*ND];
__device__ float g_KS[NB*NH*ND];

// ---------------------------------------------------------------------------
// PTX helpers (sm_80+ portable: cp.async / ldmatrix / mma.sync)
// ---------------------------------------------------------------------------
__device__ __forceinline__ uint32_t smem_to_u32(const void* p) {
    uint32_t a;
    asm("{ .reg .u64 t; cvta.to.shared.u64 t, %1; cvt.u32.u64 %0, t; }" : "=r"(a) : "l"(p));
    return a;
}
__device__ __forceinline__ void cp16(uint32_t s, const void* g) {
    asm volatile("cp.async.cg.shared.global [%0], [%1], 16;" :: "r"(s), "l"(g));
}
__device__ __forceinline__ void cp_commit() { asm volatile("cp.async.commit_group;" ::: "memory"); }
template<int N> __device__ __forceinline__ void cp_wait() {
    asm volatile("cp.async.wait_group %0;" :: "n"(N) : "memory");
}
__device__ __forceinline__ void ldm_x4(uint32_t addr, uint32_t* r) {
    asm volatile("ldmatrix.sync.aligned.m8n8.x4.shared.b16 {%0,%1,%2,%3}, [%4];"
                 : "=r"(r[0]), "=r"(r[1]), "=r"(r[2]), "=r"(r[3]) : "r"(addr));
}
__device__ __forceinline__ void mma_f16(float* d, const uint32_t* a, const uint32_t* b) {
    asm volatile("mma.sync.aligned.m16n8k16.row.col.f32.f16.f16.f32 "
                 "{%0,%1,%2,%3}, {%4,%5,%6,%7}, {%8,%9}, {%0,%1,%2,%3};"
                 : "+f"(d[0]), "+f"(d[1]), "+f"(d[2]), "+f"(d[3])
                 : "r"(a[0]), "r"(a[1]), "r"(a[2]), "r"(a[3]), "r"(b[0]), "r"(b[1]));
}

// softmax over 64 cols: 16 values per lane + quad reduction (xor 1, 2)
__device__ __forceinline__ void softmax16(float* v) {
    float mx = v[0];
    #pragma unroll
    for (int j = 1; j < 16; j++) mx = fmaxf(mx, v[j]);
    mx = fmaxf(mx, __shfl_xor_sync(0xffffffffu, mx, 1));
    mx = fmaxf(mx, __shfl_xor_sync(0xffffffffu, mx, 2));
    float s = 0.f;
    #pragma unroll
    for (int j = 0; j < 16; j++) { v[j] = __expf(v[j] - mx); s += v[j]; }
    s += __shfl_xor_sync(0xffffffffu, s, 1);
    s += __shfl_xor_sync(0xffffffffu, s, 2);
    float inv = 1.f / s;
    #pragma unroll
    for (int j = 0; j < 16; j++) v[j] *= inv;
}

// ---------------------------------------------------------------------------
// fp16 2-pass GEMM: Out[m,n] = sum_k A[m,k]*W[n,k] + bias[n], opt. softmax/64.
//   A = Ahi + Alo (fp16 split), W = fp16(W). acc = Ahi*W + Alo*W.
// CTA 128(M) x 256(N), BK=32, 4-stage cp.async pipeline.
// 8 warps as 2(M) x 4(N); warp tile 64x64.
// Smem rows padded to 40 halfwords (80B) -> conflict-free ldmatrix/cp.async.
// ---------------------------------------------------------------------------
#define BM 128
#define BN 256
#define BK 32
#define STAGES 4
#define NKT (NC/BK)                // 32
#define SROW 40                    // padded row length in halfwords
#define AMAT (128*SROW*2)          // 10240 bytes per A matrix (hi or lo)
#define BMAT (256*SROW*2)          // 20480 bytes for B matrix
#define OFF_B (2*AMAT)             // 20480
#define STG_BYTES (2*AMAT + BMAT)  // 40960
#define GSMEM (STAGES*STG_BYTES)   // 163840

__device__ __forceinline__ void gemm_body(
    const __half* __restrict__ Ahi, const __half* __restrict__ Alo,
    const __half* __restrict__ Bhi,
    const float* __restrict__ bias, float* __restrict__ Out, int do_softmax)
{
    extern __shared__ __align__(128) char sm[];
    uint32_t smb = smem_to_u32(sm);
    const int tid = threadIdx.x;
    const int m0 = blockIdx.y * BM, n0 = blockIdx.x * BN;

    const __half* a_hi = Ahi + (size_t)m0 * NC;
    const __half* a_lo = Alo + (size_t)m0 * NC;
    const __half* b_hi = Bhi + (size_t)n0 * NC;

    auto issue = [&](int stage, int k0) {
        uint32_t sb = smb + stage * STG_BYTES;
        #pragma unroll
        for (int i = 0; i < 2; i++) {                 // A hi/lo: 512 cp16 each
            int g = i * 256 + tid;
            int row = g >> 2, c = g & 3;
            uint32_t so = row * (SROW * 2) + c * 16;
            size_t  go = (size_t)row * NC + k0 + c * 8;
            cp16(sb + so,        a_hi + go);
            cp16(sb + AMAT + so, a_lo + go);
        }
        #pragma unroll
        for (int i = 0; i < 4; i++) {                 // B: 1024 cp16
            int g = i * 256 + tid;
            int row = g >> 2, c = g & 3;
            uint32_t so = row * (SROW * 2) + c * 16;
            size_t  go = (size_t)row * NC + k0 + c * 8;
            cp16(sb + OFF_B + so, b_hi + go);
        }
    };

    #pragma unroll
    for (int s = 0; s < STAGES - 1; s++) { issue(s, s * BK); cp_commit(); }

    const int wid = tid >> 5, lane = tid & 31;
    const int wm = wid & 1, wn = wid >> 1;            // warp tile: 64(M) x 64(N)

    float acc[4][8][4];
    #pragma unroll
    for (int a = 0; a < 4; a++)
        #pragma unroll
        for (int b = 0; b < 8; b++)
            #pragma unroll
            for (int c = 0; c < 4; c++) acc[a][b][c] = 0.f;

    // ldmatrix address components
    const int a_row = wm * 64 + (lane & 7) + ((lane >> 3) & 1) * 8;   // + mt*16
    const int b_row = wn * 64 + (lane & 15);                           // + p*16
    const int colb  = (lane >> 4) * 16;                                // byte offset, + ks*32

    for (int kt = 0; kt < NKT; kt++) {
        cp_wait<STAGES - 2>();
        __syncthreads();
        uint32_t sb = smb + (kt % STAGES) * STG_BYTES;
        #pragma unroll
        for (int ks = 0; ks < 2; ks++) {
            uint32_t ah[4][4], al[4][4];
            #pragma unroll
            for (int mt = 0; mt < 4; mt++) {
                uint32_t ra = sb + (a_row + mt * 16) * (SROW * 2) + ks * 32 + colb;
                ldm_x4(ra, ah[mt]);
                ldm_x4(ra + AMAT, al[mt]);
            }
            uint32_t bh[8][2];
            #pragma unroll
            for (int p = 0; p < 4; p++) {
                uint32_t rb = sb + OFF_B + (b_row + p * 16) * (SROW * 2) + ks * 32 + colb;
                uint32_t t[4];
                ldm_x4(rb, t);
                bh[2*p][0] = t[0]; bh[2*p+1][0] = t[1]; bh[2*p][1] = t[2]; bh[2*p+1][1] = t[3];
            }
            // two passes separated -> accumulator RAW distance = 32 MMAs
            #pragma unroll
            for (int mt = 0; mt < 4; mt++)
                #pragma unroll
                for (int nt = 0; nt < 8; nt++) mma_f16(acc[mt][nt], ah[mt], bh[nt]);
            #pragma unroll
            for (int mt = 0; mt < 4; mt++)
                #pragma unroll
                for (int nt = 0; nt < 8; nt++) mma_f16(acc[mt][nt], al[mt], bh[nt]);
        }
        __syncthreads();
        if (kt + STAGES - 1 < NKT) issue((kt + STAGES - 1) % STAGES, (kt + STAGES - 1) * BK);
        cp_commit();
    }

    // ---- Epilogue: bias (+softmax per 64-wide head) + store ----
    float2 bias2[8];
    const int cb = n0 + wn * 64 + (lane & 3) * 2;
    #pragma unroll
    for (int nt = 0; nt < 8; nt++)
        bias2[nt] = *reinterpret_cast<const float2*>(&bias[cb + nt * 8]);

    #pragma unroll
    for (int mt = 0; mt < 4; mt++) {
        float va[16], vb[16];
        #pragma unroll
        for (int nt = 0; nt < 8; nt++) {
            va[2*nt]   = acc[mt][nt][0] + bias2[nt].x;
            va[2*nt+1] = acc[mt][nt][1] + bias2[nt].y;
            vb[2*nt]   = acc[mt][nt][2] + bias2[nt].x;
            vb[2*nt+1] = acc[mt][nt][3] + bias2[nt].y;
        }
        if (do_softmax) { softmax16(va); softmax16(vb); }
        const int rowa = m0 + wm * 64 + mt * 16 + (lane >> 2);
        const int rowb = rowa + 8;
        #pragma unroll
        for (int nt = 0; nt < 8; nt++) {
            *reinterpret_cast<float2*>(&Out[(size_t)rowa * NC + cb + nt * 8]) =
                make_float2(va[2*nt], va[2*nt+1]);
            *reinterpret_cast<float2*>(&Out[(size_t)rowb * NC + cb + nt * 8]) =
                make_float2(vb[2*nt], vb[2*nt+1]);
        }
    }
}

__global__ __launch_bounds__(256, 1) void qkv_gemm(
    const float* __restrict__ bq, const float* __restrict__ bk, const float* __restrict__ bv)
{
    int z = blockIdx.z;
    if (z == 0)      gemm_body(g_xhi, g_xlo, g_wq, bq, g_Q, 1);
    else if (z == 1) gemm_body(g_yhi, g_ylo, g_wk, bk, g_K, 1);
    else             gemm_body(g_yhi, g_ylo, g_wv, bv, g_V, 0);
}

__global__ __launch_bounds__(256, 1) void proj_gemm(
    const float* __restrict__ bp, float* __restrict__ out)
{
    gemm_body(g_ahi, g_alo, g_wp, bp, out, 0);
}

// ---------------------------------------------------------------------------
// fp32 -> fp16 hi/lo split for activations (modes 0,1);
// fp32 -> fp16 single for weights (modes 2..5)
// ---------------------------------------------------------------------------
__global__ __launch_bounds__(256) void convert_hilo(const float* __restrict__ src, int mode)
{
    __half *dh, *dl; int n8;
    switch (mode) {
        case 0: dh = g_xhi; dl = g_xlo; n8 = NM * NC / 8; break;
        case 1: dh = g_yhi; dl = g_ylo; n8 = NM * NC / 8; break;
        case 2: dh = g_wq;  dl = nullptr; n8 = NC * NC / 8; break;
        case 3: dh = g_wk;  dl = nullptr; n8 = NC * NC / 8; break;
        case 4: dh = g_wv;  dl = nullptr; n8 = NC * NC / 8; break;
        default: dh = g_wp; dl = nullptr; n8 = NC * NC / 8; break;
    }
    int g = blockIdx.x * 256 + threadIdx.x;
    if (g >= n8) return;
    const float4* p = reinterpret_cast<const float4*>(src) + g * 2;
    float4 a = p[0], b = p[1];
    float vs[8] = {a.x, a.y, a.z, a.w, b.x, b.y, b.z, b.w};
    alignas(16) __half hi[8], lo[8];
    #pragma unroll
    for (int j = 0; j < 8; j++) {
        hi[j] = __float2half_rn(vs[j]);
        lo[j] = __float2half_rn(vs[j] - __half2float(hi[j]));
    }
    *reinterpret_cast<uint4*>(dh + (size_t)g * 8) = *reinterpret_cast<uint4*>(hi);
    if (dl) *reinterpret_cast<uint4*>(dl + (size_t)g * 8) = *reinterpret_cast<uint4*>(lo);
}

// ---------------------------------------------------------------------------
__global__ void zero_kernel()
{
    int i = blockIdx.x * blockDim.x + threadIdx.x;
    if (i < NB * NH * ND * ND) g_KV[i] = 0.f;
    if (i < NB * NH * ND)      g_KS[i] = 0.f;
}

// kv[d][e] = sum_n K[n,d]*V[n,e]; ksum[d] = sum_n K[n,d]
__global__ __launch_bounds__(256) void kv_kernel()
{
    const int bh    = blockIdx.x;
    const int split = blockIdx.y;
    const float* Kp = g_K + (size_t)(bh / NH) * NT * NC + (bh % NH) * ND;
    const float* Vp = g_V + (size_t)(bh / NH) * NT * NC + (bh % NH) * ND;

    __shared__ float Ks[32][ND];
    __shared__ float Vs[32][ND];

    const int tid = threadIdx.x;
    const int ty = tid >> 4, tx = tid & 15;

    float acc[4][4] = {};
    float ksp[4]    = {};

    const int nbase = split * (NT / KVSPLIT);
    for (int it = 0; it < (NT / KVSPLIT) / 32; it++) {
        int n0 = nbase + it * 32;
        #pragma unroll
        for (int i = 0; i < 2; i++) {
            int idx = i * 256 + tid;
            int rw = idx >> 4;
            int c4 = (idx & 15) << 2;
            *reinterpret_cast<float4*>(&Ks[rw][c4]) =
                *reinterpret_cast<const float4*>(Kp + (size_t)(n0 + rw) * NC + c4);
            *reinterpret_cast<float4*>(&Vs[rw][c4]) =
                *reinterpret_cast<const float4*>(Vp + (size_t)(n0 + rw) * NC + c4);
        }
        __syncthreads();
        #pragma unroll 8
        for (int n = 0; n < 32; n++) {
            float ra[4], rb[4];
            #pragma unroll
            for (int i = 0; i < 4; i++) ra[i] = Ks[n][ty * 4 + i];
            #pragma unroll
            for (int j = 0; j < 4; j++) rb[j] = Vs[n][tx * 4 + j];
            #pragma unroll
            for (int i = 0; i < 4; i++)
                #pragma unroll
                for (int j = 0; j < 4; j++)
                    acc[i][j] = fmaf(ra[i], rb[j], acc[i][j]);
            if (tx == 0) {
                #pragma unroll
                for (int i = 0; i < 4; i++) ksp[i] += ra[i];
            }
        }
        __syncthreads();
    }

    float* kvout = g_KV + bh * ND * ND;
    #pragma unroll
    for (int i = 0; i < 4; i++)
        #pragma unroll
        for (int j = 0; j < 4; j++)
            atomicAdd(&kvout[(ty * 4 + i) * ND + tx * 4 + j], acc[i][j]);
    if (tx == 0) {
        #pragma unroll
        for (int i = 0; i < 4; i++)
            atomicAdd(&g_KS[bh * ND + ty * 4 + i], ksp[i]);
    }
}

// out[t,e] = q[t,e] + (sum_d q[t,d]*kv[d,e]) / (sum_d q[t,d]*ksum[d])
// -> writes hi/lo fp16 row-major for the proj GEMM
__global__ __launch_bounds__(256) void attn_kernel()
{
    const int bh = blockIdx.y;
    const int b = bh / NH, h = bh % NH;
    const int t0 = blockIdx.x * 32;

    __shared__ float kvs[ND][ND];
    __shared__ float kss[ND];
    __shared__ float qs[32][ND];

    const int tid = threadIdx.x;
    const float* kvp = g_KV + bh * ND * ND;
    #pragma unroll
    for (int i = 0; i < 4; i++) {
        int idx = i * 256 + tid;
        int rw = idx >> 4, c4 = (idx & 15) << 2;
        *reinterpret_cast<float4*>(&kvs[rw][c4]) =
            *reinterpret_cast<const float4*>(kvp + rw * ND + c4);
    }
    if (tid < 16)
        *reinterpret_cast<float4*>(&kss[tid * 4]) =
            *reinterpret_cast<const float4*>(g_KS + bh * ND + tid * 4);

    const float* qp = g_Q + ((size_t)b * NT + t0) * NC + h * ND;
    #pragma unroll
    for (int i = 0; i < 2; i++) {
        int idx = i * 256 + tid;
        int rw = idx >> 4, c4 = (idx & 15) << 2;
        *reinterpret_cast<float4*>(&qs[rw][c4]) =
            *reinterpret_cast<const float4*>(qp + (size_t)rw * NC + c4);
    }
    __syncthreads();

    const int e = tid & 63, tg = tid >> 6;
    for (int tt = tg; tt < 32; tt += 4) {
        float ds = 0.f, os = 0.f;
        #pragma unroll
        for (int d = 0; d < ND; d++) {
            float qd = qs[tt][d];
            ds = fmaf(qd, kss[d], ds);
            os = fmaf(qd, kvs[d][e], os);
        }
        float val = qs[tt][e] + os / ds;
        size_t idx = ((size_t)b * NT + t0 + tt) * NC + h * ND + e;
        __half hi = __float2half_rn(val);
        g_ahi[idx] = hi;
        g_alo[idx] = __float2half_rn(val - __half2float(hi));
    }
}

// ---------------------------------------------------------------------------
extern "C" void kernel_launch(void* const* d_in, const int* in_sizes, int n_in,
                              void* d_out, int out_size)
{
    const float* x  = (const float*)d_in[0];
    const float* y  = (const float*)d_in[1];
    const float* Wq = (const float*)d_in[2];
    const float* bq = (const float*)d_in[3];
    const float* Wk = (const float*)d_in[4];
    const float* bk = (const float*)d_in[5];
    const float* Wv = (const float*)d_in[6];
    const float* bv = (const float*)d_in[7];
    const float* Wp = (const float*)d_in[8];
    const float* bp = (const float*)d_in[9];
    float* out = (float*)d_out;
    (void)in_sizes; (void)n_in; (void)out_size;

    cudaFuncSetAttribute(qkv_gemm,  cudaFuncAttributeMaxDynamicSharedMemorySize, GSMEM);
    cudaFuncSetAttribute(proj_gemm, cudaFuncAttributeMaxDynamicSharedMemorySize, GSMEM);

    // 1. fp32 -> fp16 splits
    int actg = (NM * NC / 8 + 255) / 256;
    int wg   = (NC * NC / 8 + 255) / 256;
    convert_hilo<<<actg, 256>>>(x, 0);
    convert_hilo<<<actg, 256>>>(y, 1);
    convert_hilo<<<wg, 256>>>(Wq, 2);
    convert_hilo<<<wg, 256>>>(Wk, 3);
    convert_hilo<<<wg, 256>>>(Wv, 4);
    convert_hilo<<<wg, 256>>>(Wp, 5);

    // 2. Q/K/V projections (softmax fused for Q,K)
    qkv_gemm<<<dim3(NC / BN, NM / BM, 3), 256, GSMEM>>>(bq, bk, bv);

    // 3. kv = K^T V, ksum = sum K
    zero_kernel<<<(NB * NH * ND * ND + 255) / 256, 256>>>();
    kv_kernel<<<dim3(NB * NH, KVSPLIT), 256>>>();

    // 4. linear-attention combine -> hi/lo fp16 for proj GEMM
    attn_kernel<<<dim3(NT / 32, NB * NH), 256>>>();

    // 5. output projection -> d_out
    proj_gemm<<<dim3(NC / BN, NM / BM, 1), 256, GSMEM>>>(bp, out);
}

// round 6
// speedup vs baseline: 3.6562x; 1.4087x over previous
#include <cuda_runtime.h>
#include <cuda_fp16.h>
#include <cstdint>

#define NB 4
#define NT 4096
#define NC 1024
#define NH 16
#define ND 64
#define NM (NB*NT)          // 16384 rows
#define KVSPLIT 8

// ---------------------------------------------------------------------------
// Device global scratch (allocation-free requirement)
// ---------------------------------------------------------------------------
__device__ __half g_x16[(size_t)NM*NC];
__device__ __half g_y16[(size_t)NM*NC];
__device__ __half g_a16[(size_t)NM*NC];
__device__ __half g_wq[NC*NC];
__device__ __half g_wk[NC*NC];
__device__ __half g_wv[NC*NC];
__device__ __half g_wp[NC*NC];
__device__ float g_Q[(size_t)NM*NC];
__device__ float g_K[(size_t)NM*NC];
__device__ float g_V[(size_t)NM*NC];
__device__ float g_KV[NB*NH*ND*ND];
__device__ float g_KS[NB*NH*ND];

// ---------------------------------------------------------------------------
// PTX helpers (sm_80+ portable: cp.async / ldmatrix / mma.sync)
// ---------------------------------------------------------------------------
__device__ __forceinline__ uint32_t smem_to_u32(const void* p) {
    uint32_t a;
    asm("{ .reg .u64 t; cvta.to.shared.u64 t, %1; cvt.u32.u64 %0, t; }" : "=r"(a) : "l"(p));
    return a;
}
__device__ __forceinline__ void cp16(uint32_t s, const void* g) {
    asm volatile("cp.async.cg.shared.global [%0], [%1], 16;" :: "r"(s), "l"(g));
}
__device__ __forceinline__ void cp_commit() { asm volatile("cp.async.commit_group;" ::: "memory"); }
template<int N> __device__ __forceinline__ void cp_wait() {
    asm volatile("cp.async.wait_group %0;" :: "n"(N) : "memory");
}
__device__ __forceinline__ void ldm_x4(uint32_t addr, uint32_t* r) {
    asm volatile("ldmatrix.sync.aligned.m8n8.x4.shared.b16 {%0,%1,%2,%3}, [%4];"
                 : "=r"(r[0]), "=r"(r[1]), "=r"(r[2]), "=r"(r[3]) : "r"(addr));
}
__device__ __forceinline__ void mma_f16(float* d, const uint32_t* a, const uint32_t* b) {
    asm volatile("mma.sync.aligned.m16n8k16.row.col.f32.f16.f16.f32 "
                 "{%0,%1,%2,%3}, {%4,%5,%6,%7}, {%8,%9}, {%0,%1,%2,%3};"
                 : "+f"(d[0]), "+f"(d[1]), "+f"(d[2]), "+f"(d[3])
                 : "r"(a[0]), "r"(a[1]), "r"(a[2]), "r"(a[3]), "r"(b[0]), "r"(b[1]));
}

// softmax over 64 cols: 16 values per lane + quad reduction (xor 1, 2)
__device__ __forceinline__ void softmax16(float* v) {
    float mx = v[0];
    #pragma unroll
    for (int j = 1; j < 16; j++) mx = fmaxf(mx, v[j]);
    mx = fmaxf(mx, __shfl_xor_sync(0xffffffffu, mx, 1));
    mx = fmaxf(mx, __shfl_xor_sync(0xffffffffu, mx, 2));
    float s = 0.f;
    #pragma unroll
    for (int j = 0; j < 16; j++) { v[j] = __expf(v[j] - mx); s += v[j]; }
    s += __shfl_xor_sync(0xffffffffu, s, 1);
    s += __shfl_xor_sync(0xffffffffu, s, 2);
    float inv = 1.f / s;
    #pragma unroll
    for (int j = 0; j < 16; j++) v[j] *= inv;
}

// ---------------------------------------------------------------------------
// fp16 GEMM: Out[m,n] = sum_k A[m,k]*W[n,k] + bias[n], opt. softmax per 64.
// CTA 128(M) x 256(N), BK=32, 4-stage cp.async pipeline.
// 8 warps as 2(M) x 4(N); warp tile 64x64.
// Smem rows padded to 40 halfwords (80B) -> conflict-free ldmatrix/cp.async.
// ---------------------------------------------------------------------------
#define BM 128
#define BN 256
#define BK 32
#define STAGES 4
#define NKT (NC/BK)                // 32
#define SROW 40                    // padded row length in halfwords
#define AMAT (128*SROW*2)          // 10240 bytes for A tile
#define BMAT (256*SROW*2)          // 20480 bytes for B tile
#define OFF_B AMAT                 // 10240
#define STG_BYTES (AMAT + BMAT)    // 30720
#define GSMEM (STAGES*STG_BYTES)   // 122880

__device__ __forceinline__ void gemm_body(
    const __half* __restrict__ A16, const __half* __restrict__ B16,
    const float* __restrict__ bias, float* __restrict__ Out, int do_softmax)
{
    extern __shared__ __align__(128) char sm[];
    uint32_t smb = smem_to_u32(sm);
    const int tid = threadIdx.x;
    const int m0 = blockIdx.y * BM, n0 = blockIdx.x * BN;

    const __half* a_g = A16 + (size_t)m0 * NC;
    const __half* b_g = B16 + (size_t)n0 * NC;

    auto issue = [&](int stage, int k0) {
        uint32_t sb = smb + stage * STG_BYTES;
        #pragma unroll
        for (int i = 0; i < 2; i++) {                 // A: 512 cp16
            int g = i * 256 + tid;
            int row = g >> 2, c = g & 3;
            cp16(sb + row * (SROW * 2) + c * 16, a_g + (size_t)row * NC + k0 + c * 8);
        }
        #pragma unroll
        for (int i = 0; i < 4; i++) {                 // B: 1024 cp16
            int g = i * 256 + tid;
            int row = g >> 2, c = g & 3;
            cp16(sb + OFF_B + row * (SROW * 2) + c * 16, b_g + (size_t)row * NC + k0 + c * 8);
        }
    };

    #pragma unroll
    for (int s = 0; s < STAGES - 1; s++) { issue(s, s * BK); cp_commit(); }

    const int wid = tid >> 5, lane = tid & 31;
    const int wm = wid & 1, wn = wid >> 1;            // warp tile: 64(M) x 64(N)

    float acc[4][8][4];
    #pragma unroll
    for (int a = 0; a < 4; a++)
        #pragma unroll
        for (int b = 0; b < 8; b++)
            #pragma unroll
            for (int c = 0; c < 4; c++) acc[a][b][c] = 0.f;

    // ldmatrix address components
    const int a_row = wm * 64 + (lane & 7) + ((lane >> 3) & 1) * 8;   // + mt*16
    const int b_row = wn * 64 + (lane & 15);                           // + p*16
    const int colb  = (lane >> 4) * 16;                                // byte offset, + ks*32

    for (int kt = 0; kt < NKT; kt++) {
        cp_wait<STAGES - 2>();
        __syncthreads();
        uint32_t sb = smb + (kt % STAGES) * STG_BYTES;
        #pragma unroll
        for (int ks = 0; ks < 2; ks++) {
            uint32_t ah[4][4];
            #pragma unroll
            for (int mt = 0; mt < 4; mt++) {
                uint32_t ra = sb + (a_row + mt * 16) * (SROW * 2) + ks * 32 + colb;
                ldm_x4(ra, ah[mt]);
            }
            uint32_t bh[8][2];
            #pragma unroll
            for (int p = 0; p < 4; p++) {
                uint32_t rb = sb + OFF_B + (b_row + p * 16) * (SROW * 2) + ks * 32 + colb;
                uint32_t t[4];
                ldm_x4(rb, t);
                bh[2*p][0] = t[0]; bh[2*p+1][0] = t[1]; bh[2*p][1] = t[2]; bh[2*p+1][1] = t[3];
            }
            #pragma unroll
            for (int mt = 0; mt < 4; mt++)
                #pragma unroll
                for (int nt = 0; nt < 8; nt++) mma_f16(acc[mt][nt], ah[mt], bh[nt]);
        }
        __syncthreads();
        if (kt + STAGES - 1 < NKT) issue((kt + STAGES - 1) % STAGES, (kt + STAGES - 1) * BK);
        cp_commit();
    }

    // ---- Epilogue: bias (+softmax per 64-wide head) + store ----
    float2 bias2[8];
    const int cb = n0 + wn * 64 + (lane & 3) * 2;
    #pragma unroll
    for (int nt = 0; nt < 8; nt++)
        bias2[nt] = *reinterpret_cast<const float2*>(&bias[cb + nt * 8]);

    #pragma unroll
    for (int mt = 0; mt < 4; mt++) {
        float va[16], vb[16];
        #pragma unroll
        for (int nt = 0; nt < 8; nt++) {
            va[2*nt]   = acc[mt][nt][0] + bias2[nt].x;
            va[2*nt+1] = acc[mt][nt][1] + bias2[nt].y;
            vb[2*nt]   = acc[mt][nt][2] + bias2[nt].x;
            vb[2*nt+1] = acc[mt][nt][3] + bias2[nt].y;
        }
        if (do_softmax) { softmax16(va); softmax16(vb); }
        const int rowa = m0 + wm * 64 + mt * 16 + (lane >> 2);
        const int rowb = rowa + 8;
        #pragma unroll
        for (int nt = 0; nt < 8; nt++) {
            *reinterpret_cast<float2*>(&Out[(size_t)rowa * NC + cb + nt * 8]) =
                make_float2(va[2*nt], va[2*nt+1]);
            *reinterpret_cast<float2*>(&Out[(size_t)rowb * NC + cb + nt * 8]) =
                make_float2(vb[2*nt], vb[2*nt+1]);
        }
    }
}

__global__ __launch_bounds__(256, 1) void qkv_gemm(
    const float* __restrict__ bq, const float* __restrict__ bk, const float* __restrict__ bv)
{
    int z = blockIdx.z;
    if (z == 0)      gemm_body(g_x16, g_wq, bq, g_Q, 1);
    else if (z == 1) gemm_body(g_y16, g_wk, bk, g_K, 1);
    else             gemm_body(g_y16, g_wv, bv, g_V, 0);
}

__global__ __launch_bounds__(256, 1) void proj_gemm(
    const float* __restrict__ bp, float* __restrict__ out)
{
    gemm_body(g_a16, g_wp, bp, out, 0);
}

// ---------------------------------------------------------------------------
// fp32 -> fp16 conversion
// ---------------------------------------------------------------------------
__global__ __launch_bounds__(256) void convert_f16(const float* __restrict__ src, int mode)
{
    __half* dh; int n8;
    switch (mode) {
        case 0: dh = g_x16; n8 = NM * NC / 8; break;
        case 1: dh = g_y16; n8 = NM * NC / 8; break;
        case 2: dh = g_wq;  n8 = NC * NC / 8; break;
        case 3: dh = g_wk;  n8 = NC * NC / 8; break;
        case 4: dh = g_wv;  n8 = NC * NC / 8; break;
        default: dh = g_wp; n8 = NC * NC / 8; break;
    }
    int g = blockIdx.x * 256 + threadIdx.x;
    if (g >= n8) return;
    const float4* p = reinterpret_cast<const float4*>(src) + g * 2;
    float4 a = p[0], b = p[1];
    float vs[8] = {a.x, a.y, a.z, a.w, b.x, b.y, b.z, b.w};
    alignas(16) __half h[8];
    #pragma unroll
    for (int j = 0; j < 8; j++) h[j] = __float2half_rn(vs[j]);
    *reinterpret_cast<uint4*>(dh + (size_t)g * 8) = *reinterpret_cast<uint4*>(h);
}

// ---------------------------------------------------------------------------
__global__ void zero_kernel()
{
    int i = blockIdx.x * blockDim.x + threadIdx.x;
    if (i < NB * NH * ND * ND) g_KV[i] = 0.f;
    if (i < NB * NH * ND)      g_KS[i] = 0.f;
}

// kv[d][e] = sum_n K[n,d]*V[n,e]; ksum[d] = sum_n K[n,d]
__global__ __launch_bounds__(256) void kv_kernel()
{
    const int bh    = blockIdx.x;
    const int split = blockIdx.y;
    const float* Kp = g_K + (size_t)(bh / NH) * NT * NC + (bh % NH) * ND;
    const float* Vp = g_V + (size_t)(bh / NH) * NT * NC + (bh % NH) * ND;

    __shared__ float Ks[32][ND];
    __shared__ float Vs[32][ND];

    const int tid = threadIdx.x;
    const int ty = tid >> 4, tx = tid & 15;

    float acc[4][4] = {};
    float ksp[4]    = {};

    const int nbase = split * (NT / KVSPLIT);
    for (int it = 0; it < (NT / KVSPLIT) / 32; it++) {
        int n0 = nbase + it * 32;
        #pragma unroll
        for (int i = 0; i < 2; i++) {
            int idx = i * 256 + tid;
            int rw = idx >> 4;
            int c4 = (idx & 15) << 2;
            *reinterpret_cast<float4*>(&Ks[rw][c4]) =
                *reinterpret_cast<const float4*>(Kp + (size_t)(n0 + rw) * NC + c4);
            *reinterpret_cast<float4*>(&Vs[rw][c4]) =
                *reinterpret_cast<const float4*>(Vp + (size_t)(n0 + rw) * NC + c4);
        }
        __syncthreads();
        #pragma unroll 8
        for (int n = 0; n < 32; n++) {
            float ra[4], rb[4];
            #pragma unroll
            for (int i = 0; i < 4; i++) ra[i] = Ks[n][ty * 4 + i];
            #pragma unroll
            for (int j = 0; j < 4; j++) rb[j] = Vs[n][tx * 4 + j];
            #pragma unroll
            for (int i = 0; i < 4; i++)
                #pragma unroll
                for (int j = 0; j < 4; j++)
                    acc[i][j] = fmaf(ra[i], rb[j], acc[i][j]);
            if (tx == 0) {
                #pragma unroll
                for (int i = 0; i < 4; i++) ksp[i] += ra[i];
            }
        }
        __syncthreads();
    }

    float* kvout = g_KV + bh * ND * ND;
    #pragma unroll
    for (int i = 0; i < 4; i++)
        #pragma unroll
        for (int j = 0; j < 4; j++)
            atomicAdd(&kvout[(ty * 4 + i) * ND + tx * 4 + j], acc[i][j]);
    if (tx == 0) {
        #pragma unroll
        for (int i = 0; i < 4; i++)
            atomicAdd(&g_KS[bh * ND + ty * 4 + i], ksp[i]);
    }
}

// out[t,e] = q[t,e] + (sum_d q[t,d]*kv[d,e]) / (sum_d q[t,d]*ksum[d])
// -> writes fp16 row-major for the proj GEMM
__global__ __launch_bounds__(256) void attn_kernel()
{
    const int bh = blockIdx.y;
    const int b = bh / NH, h = bh % NH;
    const int t0 = blockIdx.x * 32;

    __shared__ float kvs[ND][ND];
    __shared__ float kss[ND];
    __shared__ float qs[32][ND];

    const int tid = threadIdx.x;
    const float* kvp = g_KV + bh * ND * ND;
    #pragma unroll
    for (int i = 0; i < 4; i++) {
        int idx = i * 256 + tid;
        int rw = idx >> 4, c4 = (idx & 15) << 2;
        *reinterpret_cast<float4*>(&kvs[rw][c4]) =
            *reinterpret_cast<const float4*>(kvp + rw * ND + c4);
    }
    if (tid < 16)
        *reinterpret_cast<float4*>(&kss[tid * 4]) =
            *reinterpret_cast<const float4*>(g_KS + bh * ND + tid * 4);

    const float* qp = g_Q + ((size_t)b * NT + t0) * NC + h * ND;
    #pragma unroll
    for (int i = 0; i < 2; i++) {
        int idx = i * 256 + tid;
        int rw = idx >> 4, c4 = (idx & 15) << 2;
        *reinterpret_cast<float4*>(&qs[rw][c4]) =
            *reinterpret_cast<const float4*>(qp + (size_t)rw * NC + c4);
    }
    __syncthreads();

    const int e = tid & 63, tg = tid >> 6;
    for (int tt = tg; tt < 32; tt += 4) {
        float ds = 0.f, os = 0.f;
        #pragma unroll
        for (int d = 0; d < ND; d++) {
            float qd = qs[tt][d];
            ds = fmaf(qd, kss[d], ds);
            os = fmaf(qd, kvs[d][e], os);
        }
        float val = qs[tt][e] + os / ds;
        size_t idx = ((size_t)b * NT + t0 + tt) * NC + h * ND + e;
        g_a16[idx] = __float2half_rn(val);
    }
}

// ---------------------------------------------------------------------------
extern "C" void kernel_launch(void* const* d_in, const int* in_sizes, int n_in,
                              void* d_out, int out_size)
{
    const float* x  = (const float*)d_in[0];
    const float* y  = (const float*)d_in[1];
    const float* Wq = (const float*)d_in[2];
    const float* bq = (const float*)d_in[3];
    const float* Wk = (const float*)d_in[4];
    const float* bk = (const float*)d_in[5];
    const float* Wv = (const float*)d_in[6];
    const float* bv = (const float*)d_in[7];
    const float* Wp = (const float*)d_in[8];
    const float* bp = (const float*)d_in[9];
    float* out = (float*)d_out;
    (void)in_sizes; (void)n_in; (void)out_size;

    cudaFuncSetAttribute(qkv_gemm,  cudaFuncAttributeMaxDynamicSharedMemorySize, GSMEM);
    cudaFuncSetAttribute(proj_gemm, cudaFuncAttributeMaxDynamicSharedMemorySize, GSMEM);

    // 1. fp32 -> fp16
    int actg = (NM * NC / 8 + 255) / 256;
    int wg   = (NC * NC / 8 + 255) / 256;
    convert_f16<<<actg, 256>>>(x, 0);
    convert_f16<<<actg, 256>>>(y, 1);
    convert_f16<<<wg, 256>>>(Wq, 2);
    convert_f16<<<wg, 256>>>(Wk, 3);
    convert_f16<<<wg, 256>>>(Wv, 4);
    convert_f16<<<wg, 256>>>(Wp, 5);

    // 2. Q/K/V projections (softmax fused for Q,K)
    qkv_gemm<<<dim3(NC / BN, NM / BM, 3), 256, GSMEM>>>(bq, bk, bv);

    // 3. kv = K^T V, ksum = sum K
    zero_kernel<<<(NB * NH * ND * ND + 255) / 256, 256>>>();
    kv_kernel<<<dim3(NB * NH, KVSPLIT), 256>>>();

    // 4. linear-attention combine -> fp16 for proj GEMM
    attn_kernel<<<dim3(NT / 32, NB * NH), 256>>>();

    // 5. output projection -> d_out
    proj_gemm<<<dim3(NC / BN, NM / BM, 1), 256, GSMEM>>>(bp, out);
}

// round 8
// speedup vs baseline: 3.9216x; 1.0726x over previous
#include <cuda_runtime.h>
#include <cuda_fp16.h>
#include <cstdint>

#define NB 4
#define NT 4096
#define NC 1024
#define NH 16
#define ND 64
#define NM (NB*NT)          // 16384 rows

// ---------------------------------------------------------------------------
// Device global scratch (allocation-free requirement)
// ---------------------------------------------------------------------------
__device__ __half g_x16[(size_t)NM*NC];
__device__ __half g_y16[(size_t)NM*NC];
__device__ __half g_a16[(size_t)NM*NC];
__device__ __half g_wq[NC*NC];
__device__ __half g_wk[NC*NC];
__device__ __half g_wv[NC*NC];
__device__ __half g_wp[NC*NC];
__device__ __half g_Q[(size_t)NM*NC];
__device__ __half g_K[(size_t)NM*NC];
__device__ __half g_V[(size_t)NM*NC];
__device__ float g_KV2[2*64*64*64];   // [split][bh][d][e]
__device__ float g_KS2[2*64*64];      // [split][bh][d]

// ---------------------------------------------------------------------------
// PTX helpers (sm_80+ portable: cp.async / ldmatrix / mma.sync)
// ---------------------------------------------------------------------------
__device__ __forceinline__ uint32_t smem_to_u32(const void* p) {
    uint32_t a;
    asm("{ .reg .u64 t; cvta.to.shared.u64 t, %1; cvt.u32.u64 %0, t; }" : "=r"(a) : "l"(p));
    return a;
}
__device__ __forceinline__ void cp16(uint32_t s, const void* g) {
    asm volatile("cp.async.cg.shared.global [%0], [%1], 16;" :: "r"(s), "l"(g));
}
__device__ __forceinline__ void cp_commit() { asm volatile("cp.async.commit_group;" ::: "memory"); }
template<int N> __device__ __forceinline__ void cp_wait() {
    asm volatile("cp.async.wait_group %0;" :: "n"(N) : "memory");
}
__device__ __forceinline__ void ldm_x4(uint32_t addr, uint32_t* r) {
    asm volatile("ldmatrix.sync.aligned.m8n8.x4.shared.b16 {%0,%1,%2,%3}, [%4];"
                 : "=r"(r[0]), "=r"(r[1]), "=r"(r[2]), "=r"(r[3]) : "r"(addr));
}
__device__ __forceinline__ void ldm_x4_t(uint32_t addr, uint32_t* r) {
    asm volatile("ldmatrix.sync.aligned.m8n8.x4.trans.shared.b16 {%0,%1,%2,%3}, [%4];"
                 : "=r"(r[0]), "=r"(r[1]), "=r"(r[2]), "=r"(r[3]) : "r"(addr));
}
__device__ __forceinline__ void mma_f16(float* d, const uint32_t* a, const uint32_t* b) {
    asm volatile("mma.sync.aligned.m16n8k16.row.col.f32.f16.f16.f32 "
                 "{%0,%1,%2,%3}, {%4,%5,%6,%7}, {%8,%9}, {%0,%1,%2,%3};"
                 : "+f"(d[0]), "+f"(d[1]), "+f"(d[2]), "+f"(d[3])
                 : "r"(a[0]), "r"(a[1]), "r"(a[2]), "r"(a[3]), "r"(b[0]), "r"(b[1]));
}

// softmax over 64 cols: 16 values per lane + quad reduction (xor 1, 2)
__device__ __forceinline__ void softmax16(float* v) {
    float mx = v[0];
    #pragma unroll
    for (int j = 1; j < 16; j++) mx = fmaxf(mx, v[j]);
    mx = fmaxf(mx, __shfl_xor_sync(0xffffffffu, mx, 1));
    mx = fmaxf(mx, __shfl_xor_sync(0xffffffffu, mx, 2));
    float s = 0.f;
    #pragma unroll
    for (int j = 0; j < 16; j++) { v[j] = __expf(v[j] - mx); s += v[j]; }
    s += __shfl_xor_sync(0xffffffffu, s, 1);
    s += __shfl_xor_sync(0xffffffffu, s, 2);
    float inv = 1.f / s;
    #pragma unroll
    for (int j = 0; j < 16; j++) v[j] *= inv;
}

// ---------------------------------------------------------------------------
// fp16 GEMM: Out[m,n] = sum_k A[m,k]*W[n,k] + bias[n], opt. softmax per 64.
// CTA 128(M) x 256(N), BK=32, 4-stage cp.async pipeline; 8 warps 64x64.
// Output to fp16 (OutH) or fp32 (OutF).
// ---------------------------------------------------------------------------
#define BM 128
#define BN 256
#define BK 32
#define STAGES 4
#define NKT (NC/BK)                // 32
#define SROW 40                    // padded row length in halfwords
#define AMAT (128*SROW*2)          // 10240
#define BMAT (256*SROW*2)          // 20480
#define OFF_B AMAT
#define STG_BYTES (AMAT + BMAT)    // 30720
#define GSMEM (STAGES*STG_BYTES)   // 122880

__device__ __forceinline__ void gemm_body(
    const __half* __restrict__ A16, const __half* __restrict__ B16,
    const float* __restrict__ bias, float* __restrict__ OutF,
    __half* __restrict__ OutH, int do_softmax)
{
    extern __shared__ __align__(128) char sm[];
    uint32_t smb = smem_to_u32(sm);
    const int tid = threadIdx.x;
    const int m0 = blockIdx.y * BM, n0 = blockIdx.x * BN;

    const __half* a_g = A16 + (size_t)m0 * NC;
    const __half* b_g = B16 + (size_t)n0 * NC;

    auto issue = [&](int stage, int k0) {
        uint32_t sb = smb + stage * STG_BYTES;
        #pragma unroll
        for (int i = 0; i < 2; i++) {
            int g = i * 256 + tid;
            int row = g >> 2, c = g & 3;
            cp16(sb + row * (SROW * 2) + c * 16, a_g + (size_t)row * NC + k0 + c * 8);
        }
        #pragma unroll
        for (int i = 0; i < 4; i++) {
            int g = i * 256 + tid;
            int row = g >> 2, c = g & 3;
            cp16(sb + OFF_B + row * (SROW * 2) + c * 16, b_g + (size_t)row * NC + k0 + c * 8);
        }
    };

    #pragma unroll
    for (int s = 0; s < STAGES - 1; s++) { issue(s, s * BK); cp_commit(); }

    const int wid = tid >> 5, lane = tid & 31;
    const int wm = wid & 1, wn = wid >> 1;

    float acc[4][8][4];
    #pragma unroll
    for (int a = 0; a < 4; a++)
        #pragma unroll
        for (int b = 0; b < 8; b++)
            #pragma unroll
            for (int c = 0; c < 4; c++) acc[a][b][c] = 0.f;

    const int a_row = wm * 64 + (lane & 7) + ((lane >> 3) & 1) * 8;
    const int b_row = wn * 64 + (lane & 15);
    const int colb  = (lane >> 4) * 16;

    for (int kt = 0; kt < NKT; kt++) {
        cp_wait<STAGES - 2>();
        __syncthreads();
        uint32_t sb = smb + (kt % STAGES) * STG_BYTES;
        #pragma unroll
        for (int ks = 0; ks < 2; ks++) {
            uint32_t ah[4][4];
            #pragma unroll
            for (int mt = 0; mt < 4; mt++)
                ldm_x4(sb + (a_row + mt * 16) * (SROW * 2) + ks * 32 + colb, ah[mt]);
            uint32_t bh[8][2];
            #pragma unroll
            for (int p = 0; p < 4; p++) {
                uint32_t t[4];
                ldm_x4(sb + OFF_B + (b_row + p * 16) * (SROW * 2) + ks * 32 + colb, t);
                bh[2*p][0] = t[0]; bh[2*p+1][0] = t[1]; bh[2*p][1] = t[2]; bh[2*p+1][1] = t[3];
            }
            #pragma unroll
            for (int mt = 0; mt < 4; mt++)
                #pragma unroll
                for (int nt = 0; nt < 8; nt++) mma_f16(acc[mt][nt], ah[mt], bh[nt]);
        }
        __syncthreads();
        if (kt + STAGES - 1 < NKT) issue((kt + STAGES - 1) % STAGES, (kt + STAGES - 1) * BK);
        cp_commit();
    }

    // ---- Epilogue ----
    float2 bias2[8];
    const int cb = n0 + wn * 64 + (lane & 3) * 2;
    #pragma unroll
    for (int nt = 0; nt < 8; nt++)
        bias2[nt] = *reinterpret_cast<const float2*>(&bias[cb + nt * 8]);

    #pragma unroll
    for (int mt = 0; mt < 4; mt++) {
        float va[16], vb[16];
        #pragma unroll
        for (int nt = 0; nt < 8; nt++) {
            va[2*nt]   = acc[mt][nt][0] + bias2[nt].x;
            va[2*nt+1] = acc[mt][nt][1] + bias2[nt].y;
            vb[2*nt]   = acc[mt][nt][2] + bias2[nt].x;
            vb[2*nt+1] = acc[mt][nt][3] + bias2[nt].y;
        }
        if (do_softmax) { softmax16(va); softmax16(vb); }
        const int rowa = m0 + wm * 64 + mt * 16 + (lane >> 2);
        const int rowb = rowa + 8;
        if (OutH) {
            #pragma unroll
            for (int nt = 0; nt < 8; nt++) {
                *reinterpret_cast<__half2*>(&OutH[(size_t)rowa * NC + cb + nt * 8]) =
                    __floats2half2_rn(va[2*nt], va[2*nt+1]);
                *reinterpret_cast<__half2*>(&OutH[(size_t)rowb * NC + cb + nt * 8]) =
                    __floats2half2_rn(vb[2*nt], vb[2*nt+1]);
            }
        } else {
            #pragma unroll
            for (int nt = 0; nt < 8; nt++) {
                *reinterpret_cast<float2*>(&OutF[(size_t)rowa * NC + cb + nt * 8]) =
                    make_float2(va[2*nt], va[2*nt+1]);
                *reinterpret_cast<float2*>(&OutF[(size_t)rowb * NC + cb + nt * 8]) =
                    make_float2(vb[2*nt], vb[2*nt+1]);
            }
        }
    }
}

__global__ __launch_bounds__(256, 1) void qkv_gemm(
    const float* __restrict__ bq, const float* __restrict__ bk, const float* __restrict__ bv)
{
    int z = blockIdx.z;
    if (z == 0)      gemm_body(g_x16, g_wq, bq, nullptr, g_Q, 1);
    else if (z == 1) gemm_body(g_y16, g_wk, bk, nullptr, g_K, 1);
    else             gemm_body(g_y16, g_wv, bv, nullptr, g_V, 0);
}

__global__ __launch_bounds__(256, 1) void proj_gemm(
    const float* __restrict__ bp, float* __restrict__ out)
{
    gemm_body(g_a16, g_wp, bp, out, nullptr, 0);
}

// ---------------------------------------------------------------------------
// fp32 -> fp16 converts (merged launches)
// ---------------------------------------------------------------------------
__global__ __launch_bounds__(256) void convert_act(const float* __restrict__ x,
                                                   const float* __restrict__ y)
{
    const float* src = blockIdx.y ? y : x;
    __half* dh = blockIdx.y ? g_y16 : g_x16;
    int g = blockIdx.x * 256 + threadIdx.x;            // one per 8 elems
    const float4* p = reinterpret_cast<const float4*>(src) + (size_t)g * 2;
    float4 a = p[0], b = p[1];
    alignas(16) __half h[8] = {
        __float2half_rn(a.x), __float2half_rn(a.y), __float2half_rn(a.z), __float2half_rn(a.w),
        __float2half_rn(b.x), __float2half_rn(b.y), __float2half_rn(b.z), __float2half_rn(b.w) };
    *reinterpret_cast<uint4*>(dh + (size_t)g * 8) = *reinterpret_cast<uint4*>(h);
}

__global__ __launch_bounds__(256) void convert_w(const float* __restrict__ wq,
                                                 const float* __restrict__ wk,
                                                 const float* __restrict__ wv,
                                                 const float* __restrict__ wp)
{
    const float* src; __half* dh;
    switch (blockIdx.y) {
        case 0: src = wq; dh = g_wq; break;
        case 1: src = wk; dh = g_wk; break;
        case 2: src = wv; dh = g_wv; break;
        default: src = wp; dh = g_wp; break;
    }
    int g = blockIdx.x * 256 + threadIdx.x;
    const float4* p = reinterpret_cast<const float4*>(src) + (size_t)g * 2;
    float4 a = p[0], b = p[1];
    alignas(16) __half h[8] = {
        __float2half_rn(a.x), __float2half_rn(a.y), __float2half_rn(a.z), __float2half_rn(a.w),
        __float2half_rn(b.x), __float2half_rn(b.y), __float2half_rn(b.z), __float2half_rn(b.w) };
    *reinterpret_cast<uint4*>(dh + (size_t)g * 8) = *reinterpret_cast<uint4*>(h);
}

// ---------------------------------------------------------------------------
// kv via HMMA: kv[d][e] = sum_n K[n,d]*V[n,e]; ksum[d] = sum_n K[n,d]
// grid (64 bh, 2 splits), 256 thr (8 warps as 4(d) x 2(e)); warp = d16 x e32.
// K/V tiles 128 tok x 64, smem rows padded to 88 halfs (176B = 44-bank step,
// conflict-free). V pad cols 64-79 initialized: col64 = 1.0, 65-79 = 0 ->
// ksum via one extra MMA on wn==1 warps (reads cols 64-79, in bounds).
// K pad is never read (A-loads stay <= col 63). ldmatrix.trans.
// ---------------------------------------------------------------------------
#define KV_ROW 176                 // bytes per smem row (88 halfs)
#define KV_MAT (128*KV_ROW)        // 22528
#define KV_STG (2*KV_MAT)          // 45056 (K then V)
#define KV_SMEM (2*KV_STG)         // 90112
#define KV_TILES 16                // 2048 tokens per split / 128

__global__ __launch_bounds__(256, 1) void kv_hmma()
{
    extern __shared__ __align__(128) char sm[];
    uint32_t smb = smem_to_u32(sm);
    const int bh = blockIdx.x, split = blockIdx.y;
    const int tid = threadIdx.x, wid = tid >> 5, lane = tid & 31;
    const int wm = wid & 3, wn = wid >> 2;
    const int m0 = wm * 16, n0 = wn * 32;
    const int lr = lane & 7, lg = lane >> 3;

    const __half* Kp = g_K + (size_t)(bh / NH) * NT * NC + (bh % NH) * ND;
    const __half* Vp = g_V + (size_t)(bh / NH) * NT * NC + (bh % NH) * ND;
    const int tokbase = split * 2048;

    auto issue = [&](int stage, int tile) {
        uint32_t sb = smb + stage * KV_STG;
        int t0 = tokbase + tile * 128;
        #pragma unroll
        for (int i = 0; i < 4; i++) {
            int slot = i * 256 + tid;                  // 1024 slots
            int row = slot >> 3, c = slot & 7;
            cp16(sb + row * KV_ROW + c * 16,          Kp + (size_t)(t0 + row) * NC + c * 8);
            cp16(sb + KV_MAT + row * KV_ROW + c * 16, Vp + (size_t)(t0 + row) * NC + c * 8);
        }
        // V pad cols 64-79: col64 = 1.0, rest 0 (ones column for ksum).
        // 128 rows x 2 uint4 = 256 writes, one per thread.
        int row = tid >> 1, which = tid & 1;
        uint4 padv = which ? make_uint4(0u, 0u, 0u, 0u)
                           : make_uint4(0x00003C00u, 0u, 0u, 0u);
        *reinterpret_cast<uint4*>(sm + stage * KV_STG + KV_MAT + row * KV_ROW + 128 + which * 16) = padv;
    };

    float acc[4][4] = {};     // 4 n-tiles of 8 (e = n0 + 8j)
    float accS[4]   = {};     // ksum tile (cols 64-71), wn==1 only

    issue(0, 0); cp_commit();

    for (int tile = 0; tile < KV_TILES; tile++) {
        if (tile + 1 < KV_TILES) { issue((tile + 1) & 1, tile + 1); cp_commit(); cp_wait<1>(); }
        else cp_wait<0>();
        __syncthreads();
        uint32_t kb = smb + (tile & 1) * KV_STG;
        uint32_t vb = kb + KV_MAT;
        #pragma unroll
        for (int s = 0; s < 8; s++) {
            int ts = s * 16;
            uint32_t a[4];
            ldm_x4_t(kb + (ts + lr + (lg >> 1) * 8) * KV_ROW + (m0 + (lg & 1) * 8) * 2, a);
            #pragma unroll
            for (int eg = 0; eg < 2; eg++) {
                uint32_t t[4];
                ldm_x4_t(vb + (ts + lr + (lg & 1) * 8) * KV_ROW + (n0 + eg * 16 + (lg >> 1) * 8) * 2, t);
                mma_f16(acc[eg * 2 + 0], a, t + 0);   // {t0, t1}
                mma_f16(acc[eg * 2 + 1], a, t + 2);   // {t2, t3}
            }
            if (wn == 1) {
                uint32_t t[4];
                ldm_x4_t(vb + (ts + lr + (lg & 1) * 8) * KV_ROW + (64 + (lg >> 1) * 8) * 2, t);
                mma_f16(accS, a, t + 0);
            }
        }
        __syncthreads();
    }

    float* kvout = g_KV2 + ((size_t)split * 64 + bh) * 4096;
    const int r0 = m0 + (lane >> 2), c0 = (lane & 3) * 2;
    #pragma unroll
    for (int j = 0; j < 4; j++) {
        *reinterpret_cast<float2*>(&kvout[r0 * 64 + n0 + j * 8 + c0]) =
            make_float2(acc[j][0], acc[j][1]);
        *reinterpret_cast<float2*>(&kvout[(r0 + 8) * 64 + n0 + j * 8 + c0]) =
            make_float2(acc[j][2], acc[j][3]);
    }
    if (wn == 1 && (lane & 3) == 0) {
        float* ksout = g_KS2 + ((size_t)split * 64 + bh) * 64;
        ksout[m0 + (lane >> 2)]     = accS[0];
        ksout[m0 + 8 + (lane >> 2)] = accS[2];
    }
}

// ---------------------------------------------------------------------------
// out[t,e] = q[t,e] + (sum_d q[t,d]*kv[d,e]) / (sum_d q[t,d]*ksum[d])
// Q fp16 in, fp16 out for proj GEMM. kv/ks summed from 2 split buffers.
// ---------------------------------------------------------------------------
__global__ __launch_bounds__(256) void attn_kernel()
{
    const int bh = blockIdx.y;
    const int b = bh / NH, h = bh % NH;
    const int t0 = blockIdx.x * 32;

    __shared__ float kvs[ND][ND];
    __shared__ float kss[ND];
    __shared__ float qs[32][ND];

    const int tid = threadIdx.x;
    const float* kv0 = g_KV2 + (size_t)bh * 4096;
    const float* kv1 = g_KV2 + (size_t)(64 + bh) * 4096;
    #pragma unroll
    for (int i = 0; i < 4; i++) {
        int idx = i * 256 + tid;
        int rw = idx >> 4, c4 = (idx & 15) << 2;
        float4 a = *reinterpret_cast<const float4*>(kv0 + rw * 64 + c4);
        float4 c = *reinterpret_cast<const float4*>(kv1 + rw * 64 + c4);
        kvs[rw][c4] = a.x + c.x; kvs[rw][c4+1] = a.y + c.y;
        kvs[rw][c4+2] = a.z + c.z; kvs[rw][c4+3] = a.w + c.w;
    }
    if (tid < 64) kss[tid] = g_KS2[bh * 64 + tid] + g_KS2[64 * 64 + bh * 64 + tid];

    const __half* qp = g_Q + ((size_t)b * NT + t0) * NC + h * ND;
    {
        int rw = tid >> 3, c8 = (tid & 7) * 8;
        uint4 raw = *reinterpret_cast<const uint4*>(qp + (size_t)rw * NC + c8);
        const __half2* hp = reinterpret_cast<const __half2*>(&raw);
        #pragma unroll
        for (int j = 0; j < 4; j++) {
            float2 f = __half22float2(hp[j]);
            qs[rw][c8 + 2*j] = f.x; qs[rw][c8 + 2*j + 1] = f.y;
        }
    }
    __syncthreads();

    const int e = tid & 63, tg = tid >> 6;
    for (int tt = tg; tt < 32; tt += 4) {
        float ds = 0.f, os = 0.f;
        #pragma unroll
        for (int d = 0; d < ND; d++) {
            float qd = qs[tt][d];
            ds = fmaf(qd, kss[d], ds);
            os = fmaf(qd, kvs[d][e], os);
        }
        float val = qs[tt][e] + os / ds;
        g_a16[((size_t)b * NT + t0 + tt) * NC + h * ND + e] = __float2half_rn(val);
    }
}

// ---------------------------------------------------------------------------
extern "C" void kernel_launch(void* const* d_in, const int* in_sizes, int n_in,
                              void* d_out, int out_size)
{
    const float* x  = (const float*)d_in[0];
    const float* y  = (const float*)d_in[1];
    const float* Wq = (const float*)d_in[2];
    const float* bq = (const float*)d_in[3];
    const float* Wk = (const float*)d_in[4];
    const float* bk = (const float*)d_in[5];
    const float* Wv = (const float*)d_in[6];
    const float* bv = (const float*)d_in[7];
    const float* Wp = (const float*)d_in[8];
    const float* bp = (const float*)d_in[9];
    float* out = (float*)d_out;
    (void)in_sizes; (void)n_in; (void)out_size;

    cudaFuncSetAttribute(qkv_gemm,  cudaFuncAttributeMaxDynamicSharedMemorySize, GSMEM);
    cudaFuncSetAttribute(proj_gemm, cudaFuncAttributeMaxDynamicSharedMemorySize, GSMEM);
    cudaFuncSetAttribute(kv_hmma,   cudaFuncAttributeMaxDynamicSharedMemorySize, KV_SMEM);

    // 1. fp32 -> fp16 (merged)
    convert_act<<<dim3(NM * NC / 8 / 256, 2), 256>>>(x, y);
    convert_w<<<dim3(NC * NC / 8 / 256, 4), 256>>>(Wq, Wk, Wv, Wp);

    // 2. Q/K/V projections (softmax fused for Q,K) -> fp16
    qkv_gemm<<<dim3(NC / BN, NM / BM, 3), 256, GSMEM>>>(bq, bk, bv);

    // 3. kv = K^T V (+ksum via ones column) on tensor cores, 2-way T split
    kv_hmma<<<dim3(NB * NH, 2), 256, KV_SMEM>>>();

    // 4. linear-attention combine -> fp16 for proj GEMM
    attn_kernel<<<dim3(NT / 32, NB * NH), 256>>>();

    // 5. output projection -> d_out (fp32)
    proj_gemm<<<dim3(NC / BN, NM / BM, 1), 256, GSMEM>>>(bp, out);
}

// round 9
// speedup vs baseline: 4.4689x; 1.1396x over previous
#include <cuda_runtime.h>
#include <cuda_fp16.h>
#include <cstdint>

#define NB 4
#define NT 4096
#define NC 1024
#define NH 16
#define ND 64
#define NM (NB*NT)          // 16384 rows
#define KVSPL 4

// ---------------------------------------------------------------------------
// Device global scratch (allocation-free requirement)
// ---------------------------------------------------------------------------
__device__ __half g_x16[(size_t)NM*NC];
__device__ __half g_y16[(size_t)NM*NC];
__device__ __half g_a16[(size_t)NM*NC];
__device__ __half g_wq[NC*NC];
__device__ __half g_wk[NC*NC];
__device__ __half g_wv[NC*NC];
__device__ __half g_wp[NC*NC];
__device__ __half g_Q[(size_t)NM*NC];
__device__ __half g_K[(size_t)NM*NC];
__device__ __half g_V[(size_t)NM*NC];
__device__ float g_KV2[KVSPL*64*64*64];   // [split][bh][d][e]
__device__ float g_KS2[KVSPL*64*64];      // [split][bh][d]

// ---------------------------------------------------------------------------
// PTX helpers (sm_80+ portable: cp.async / ldmatrix / mma.sync)
// ---------------------------------------------------------------------------
__device__ __forceinline__ uint32_t smem_to_u32(const void* p) {
    uint32_t a;
    asm("{ .reg .u64 t; cvta.to.shared.u64 t, %1; cvt.u32.u64 %0, t; }" : "=r"(a) : "l"(p));
    return a;
}
__device__ __forceinline__ void cp16(uint32_t s, const void* g) {
    asm volatile("cp.async.cg.shared.global [%0], [%1], 16;" :: "r"(s), "l"(g));
}
__device__ __forceinline__ void cp_commit() { asm volatile("cp.async.commit_group;" ::: "memory"); }
template<int N> __device__ __forceinline__ void cp_wait() {
    asm volatile("cp.async.wait_group %0;" :: "n"(N) : "memory");
}
__device__ __forceinline__ void ldm_x4(uint32_t addr, uint32_t* r) {
    asm volatile("ldmatrix.sync.aligned.m8n8.x4.shared.b16 {%0,%1,%2,%3}, [%4];"
                 : "=r"(r[0]), "=r"(r[1]), "=r"(r[2]), "=r"(r[3]) : "r"(addr));
}
__device__ __forceinline__ void ldm_x4_t(uint32_t addr, uint32_t* r) {
    asm volatile("ldmatrix.sync.aligned.m8n8.x4.trans.shared.b16 {%0,%1,%2,%3}, [%4];"
                 : "=r"(r[0]), "=r"(r[1]), "=r"(r[2]), "=r"(r[3]) : "r"(addr));
}
__device__ __forceinline__ void mma_f16(float* d, const uint32_t* a, const uint32_t* b) {
    asm volatile("mma.sync.aligned.m16n8k16.row.col.f32.f16.f16.f32 "
                 "{%0,%1,%2,%3}, {%4,%5,%6,%7}, {%8,%9}, {%0,%1,%2,%3};"
                 : "+f"(d[0]), "+f"(d[1]), "+f"(d[2]), "+f"(d[3])
                 : "r"(a[0]), "r"(a[1]), "r"(a[2]), "r"(a[3]), "r"(b[0]), "r"(b[1]));
}

// softmax over 64 cols: 16 values per lane + quad reduction (xor 1, 2)
__device__ __forceinline__ void softmax16(float* v) {
    float mx = v[0];
    #pragma unroll
    for (int j = 1; j < 16; j++) mx = fmaxf(mx, v[j]);
    mx = fmaxf(mx, __shfl_xor_sync(0xffffffffu, mx, 1));
    mx = fmaxf(mx, __shfl_xor_sync(0xffffffffu, mx, 2));
    float s = 0.f;
    #pragma unroll
    for (int j = 0; j < 16; j++) { v[j] = __expf(v[j] - mx); s += v[j]; }
    s += __shfl_xor_sync(0xffffffffu, s, 1);
    s += __shfl_xor_sync(0xffffffffu, s, 2);
    float inv = 1.f / s;
    #pragma unroll
    for (int j = 0; j < 16; j++) v[j] *= inv;
}

// ---------------------------------------------------------------------------
// fp16 GEMM: Out[m,n] = sum_k A[m,k]*W[n,k] + bias[n], opt. softmax per 64.
// CTA 128(M) x 128(N), BK=32, 4-stage cp.async pipeline; 8 warps as 4(M)x2(N)
// with 32x64 warp tiles -> ~120 regs -> 2 CTAs/SM (bubble covering).
// One __syncthreads per kt: stage kt+3 (== kt-1 mod 4) is safe to overwrite
// after the barrier since all warps finished reading it in iteration kt-1.
// ---------------------------------------------------------------------------
#define BM 128
#define BN 128
#define BK 32
#define STAGES 4
#define NKT (NC/BK)                // 32
#define SROW 40                    // padded row length in halfwords
#define AMAT (128*SROW*2)          // 10240
#define OFF_B AMAT
#define STG_BYTES (2*AMAT)         // 20480
#define GSMEM (STAGES*STG_BYTES)   // 81920

__device__ __forceinline__ void gemm_body(
    const __half* __restrict__ A16, const __half* __restrict__ B16,
    const float* __restrict__ bias, float* __restrict__ OutF,
    __half* __restrict__ OutH, int do_softmax)
{
    extern __shared__ __align__(128) char sm[];
    uint32_t smb = smem_to_u32(sm);
    const int tid = threadIdx.x;
    const int m0 = blockIdx.y * BM, n0 = blockIdx.x * BN;

    const __half* a_g = A16 + (size_t)m0 * NC;
    const __half* b_g = B16 + (size_t)n0 * NC;

    auto issue = [&](int stage, int k0) {
        uint32_t sb = smb + stage * STG_BYTES;
        #pragma unroll
        for (int i = 0; i < 2; i++) {                 // A and B: 512 cp16 each
            int g = i * 256 + tid;
            int row = g >> 2, c = g & 3;
            uint32_t so = row * (SROW * 2) + c * 16;
            size_t  go = (size_t)row * NC + k0 + c * 8;
            cp16(sb + so,         a_g + go);
            cp16(sb + OFF_B + so, b_g + go);
        }
    };

    #pragma unroll
    for (int s = 0; s < STAGES - 1; s++) { issue(s, s * BK); cp_commit(); }

    const int wid = tid >> 5, lane = tid & 31;
    const int wm = wid & 3, wn = wid >> 2;            // warp tile: 32(M) x 64(N)

    float acc[2][8][4];
    #pragma unroll
    for (int a = 0; a < 2; a++)
        #pragma unroll
        for (int b = 0; b < 8; b++)
            #pragma unroll
            for (int c = 0; c < 4; c++) acc[a][b][c] = 0.f;

    const int a_row = wm * 32 + (lane & 7) + ((lane >> 3) & 1) * 8;   // + mt*16
    const int b_row = wn * 64 + (lane & 15);                           // + p*16
    const int colb  = (lane >> 4) * 16;                                // + ks*32

    for (int kt = 0; kt < NKT; kt++) {
        cp_wait<STAGES - 2>();
        __syncthreads();
        if (kt + STAGES - 1 < NKT) issue((kt + STAGES - 1) % STAGES, (kt + STAGES - 1) * BK);
        cp_commit();
        uint32_t sb = smb + (kt % STAGES) * STG_BYTES;
        #pragma unroll
        for (int ks = 0; ks < 2; ks++) {
            uint32_t ah[2][4];
            #pragma unroll
            for (int mt = 0; mt < 2; mt++)
                ldm_x4(sb + (a_row + mt * 16) * (SROW * 2) + ks * 32 + colb, ah[mt]);
            uint32_t bh[8][2];
            #pragma unroll
            for (int p = 0; p < 4; p++) {
                uint32_t t[4];
                ldm_x4(sb + OFF_B + (b_row + p * 16) * (SROW * 2) + ks * 32 + colb, t);
                bh[2*p][0] = t[0]; bh[2*p+1][0] = t[1]; bh[2*p][1] = t[2]; bh[2*p+1][1] = t[3];
            }
            #pragma unroll
            for (int mt = 0; mt < 2; mt++)
                #pragma unroll
                for (int nt = 0; nt < 8; nt++) mma_f16(acc[mt][nt], ah[mt], bh[nt]);
        }
    }

    // ---- Epilogue: bias (+softmax per 64-wide head) + store ----
    float2 bias2[8];
    const int cb = n0 + wn * 64 + (lane & 3) * 2;
    #pragma unroll
    for (int nt = 0; nt < 8; nt++)
        bias2[nt] = *reinterpret_cast<const float2*>(&bias[cb + nt * 8]);

    #pragma unroll
    for (int mt = 0; mt < 2; mt++) {
        float va[16], vb[16];
        #pragma unroll
        for (int nt = 0; nt < 8; nt++) {
            va[2*nt]   = acc[mt][nt][0] + bias2[nt].x;
            va[2*nt+1] = acc[mt][nt][1] + bias2[nt].y;
            vb[2*nt]   = acc[mt][nt][2] + bias2[nt].x;
            vb[2*nt+1] = acc[mt][nt][3] + bias2[nt].y;
        }
        if (do_softmax) { softmax16(va); softmax16(vb); }
        const int rowa = m0 + wm * 32 + mt * 16 + (lane >> 2);
        const int rowb = rowa + 8;
        if (OutH) {
            #pragma unroll
            for (int nt = 0; nt < 8; nt++) {
                *reinterpret_cast<__half2*>(&OutH[(size_t)rowa * NC + cb + nt * 8]) =
                    __floats2half2_rn(va[2*nt], va[2*nt+1]);
                *reinterpret_cast<__half2*>(&OutH[(size_t)rowb * NC + cb + nt * 8]) =
                    __floats2half2_rn(vb[2*nt], vb[2*nt+1]);
            }
        } else {
            #pragma unroll
            for (int nt = 0; nt < 8; nt++) {
                *reinterpret_cast<float2*>(&OutF[(size_t)rowa * NC + cb + nt * 8]) =
                    make_float2(va[2*nt], va[2*nt+1]);
                *reinterpret_cast<float2*>(&OutF[(size_t)rowb * NC + cb + nt * 8]) =
                    make_float2(vb[2*nt], vb[2*nt+1]);
            }
        }
    }
}

__global__ __launch_bounds__(256, 2) void qkv_gemm(
    const float* __restrict__ bq, const float* __restrict__ bk, const float* __restrict__ bv)
{
    int z = blockIdx.z;
    if (z == 0)      gemm_body(g_x16, g_wq, bq, nullptr, g_Q, 1);
    else if (z == 1) gemm_body(g_y16, g_wk, bk, nullptr, g_K, 1);
    else             gemm_body(g_y16, g_wv, bv, nullptr, g_V, 0);
}

__global__ __launch_bounds__(256, 2) void proj_gemm(
    const float* __restrict__ bp, float* __restrict__ out)
{
    gemm_body(g_a16, g_wp, bp, out, nullptr, 0);
}

// ---------------------------------------------------------------------------
// fp32 -> fp16 converts (merged launches)
// ---------------------------------------------------------------------------
__global__ __launch_bounds__(256) void convert_act(const float* __restrict__ x,
                                                   const float* __restrict__ y)
{
    const float* src = blockIdx.y ? y : x;
    __half* dh = blockIdx.y ? g_y16 : g_x16;
    int g = blockIdx.x * 256 + threadIdx.x;
    const float4* p = reinterpret_cast<const float4*>(src) + (size_t)g * 2;
    float4 a = p[0], b = p[1];
    alignas(16) __half h[8] = {
        __float2half_rn(a.x), __float2half_rn(a.y), __float2half_rn(a.z), __float2half_rn(a.w),
        __float2half_rn(b.x), __float2half_rn(b.y), __float2half_rn(b.z), __float2half_rn(b.w) };
    *reinterpret_cast<uint4*>(dh + (size_t)g * 8) = *reinterpret_cast<uint4*>(h);
}

__global__ __launch_bounds__(256) void convert_w(const float* __restrict__ wq,
                                                 const float* __restrict__ wk,
                                                 const float* __restrict__ wv,
                                                 const float* __restrict__ wp)
{
    const float* src; __half* dh;
    switch (blockIdx.y) {
        case 0: src = wq; dh = g_wq; break;
        case 1: src = wk; dh = g_wk; break;
        case 2: src = wv; dh = g_wv; break;
        default: src = wp; dh = g_wp; break;
    }
    int g = blockIdx.x * 256 + threadIdx.x;
    const float4* p = reinterpret_cast<const float4*>(src) + (size_t)g * 2;
    float4 a = p[0], b = p[1];
    alignas(16) __half h[8] = {
        __float2half_rn(a.x), __float2half_rn(a.y), __float2half_rn(a.z), __float2half_rn(a.w),
        __float2half_rn(b.x), __float2half_rn(b.y), __float2half_rn(b.z), __float2half_rn(b.w) };
    *reinterpret_cast<uint4*>(dh + (size_t)g * 8) = *reinterpret_cast<uint4*>(h);
}

// ---------------------------------------------------------------------------
// kv via HMMA: kv[d][e] = sum_n K[n,d]*V[n,e]; ksum[d] = sum_n K[n,d]
// grid (64 bh, KVSPL splits), 256 thr (8 warps as 4(d) x 2(e)).
// K/V tiles 128 tok x 64, rows padded to 88 halfs (176B, conflict-free);
// V pad cols 64-79: col64 = 1.0 (ones column -> ksum on wn==1 warps).
// ---------------------------------------------------------------------------
#define KV_ROW 176                 // bytes per smem row (88 halfs)
#define KV_MAT (128*KV_ROW)        // 22528
#define KV_STG (2*KV_MAT)          // 45056 (K then V)
#define KV_SMEM (2*KV_STG)         // 90112
#define KV_TILES (NT/KVSPL/128)    // 8

__global__ __launch_bounds__(256, 1) void kv_hmma()
{
    extern __shared__ __align__(128) char sm[];
    uint32_t smb = smem_to_u32(sm);
    const int bh = blockIdx.x, split = blockIdx.y;
    const int tid = threadIdx.x, wid = tid >> 5, lane = tid & 31;
    const int wm = wid & 3, wn = wid >> 2;
    const int m0 = wm * 16, n0 = wn * 32;
    const int lr = lane & 7, lg = lane >> 3;

    const __half* Kp = g_K + (size_t)(bh / NH) * NT * NC + (bh % NH) * ND;
    const __half* Vp = g_V + (size_t)(bh / NH) * NT * NC + (bh % NH) * ND;
    const int tokbase = split * (NT / KVSPL);

    auto issue = [&](int stage, int tile) {
        uint32_t sb = smb + stage * KV_STG;
        int t0 = tokbase + tile * 128;
        #pragma unroll
        for (int i = 0; i < 4; i++) {
            int slot = i * 256 + tid;
            int row = slot >> 3, c = slot & 7;
            cp16(sb + row * KV_ROW + c * 16,          Kp + (size_t)(t0 + row) * NC + c * 8);
            cp16(sb + KV_MAT + row * KV_ROW + c * 16, Vp + (size_t)(t0 + row) * NC + c * 8);
        }
        int row = tid >> 1, which = tid & 1;
        uint4 padv = which ? make_uint4(0u, 0u, 0u, 0u)
                           : make_uint4(0x00003C00u, 0u, 0u, 0u);
        *reinterpret_cast<uint4*>(sm + stage * KV_STG + KV_MAT + row * KV_ROW + 128 + which * 16) = padv;
    };

    float acc[4][4] = {};
    float accS[4]   = {};

    issue(0, 0); cp_commit();

    for (int tile = 0; tile < KV_TILES; tile++) {
        if (tile + 1 < KV_TILES) { issue((tile + 1) & 1, tile + 1); cp_commit(); cp_wait<1>(); }
        else cp_wait<0>();
        __syncthreads();
        uint32_t kb = smb + (tile & 1) * KV_STG;
        uint32_t vb = kb + KV_MAT;
        #pragma unroll
        for (int s = 0; s < 8; s++) {
            int ts = s * 16;
            uint32_t a[4];
            ldm_x4_t(kb + (ts + lr + (lg >> 1) * 8) * KV_ROW + (m0 + (lg & 1) * 8) * 2, a);
            #pragma unroll
            for (int eg = 0; eg < 2; eg++) {
                uint32_t t[4];
                ldm_x4_t(vb + (ts + lr + (lg & 1) * 8) * KV_ROW + (n0 + eg * 16 + (lg >> 1) * 8) * 2, t);
                mma_f16(acc[eg * 2 + 0], a, t + 0);
                mma_f16(acc[eg * 2 + 1], a, t + 2);
            }
            if (wn == 1) {
                uint32_t t[4];
                ldm_x4_t(vb + (ts + lr + (lg & 1) * 8) * KV_ROW + (64 + (lg >> 1) * 8) * 2, t);
                mma_f16(accS, a, t + 0);
            }
        }
        __syncthreads();
    }

    float* kvout = g_KV2 + ((size_t)split * 64 + bh) * 4096;
    const int r0 = m0 + (lane >> 2), c0 = (lane & 3) * 2;
    #pragma unroll
    for (int j = 0; j < 4; j++) {
        *reinterpret_cast<float2*>(&kvout[r0 * 64 + n0 + j * 8 + c0]) =
            make_float2(acc[j][0], acc[j][1]);
        *reinterpret_cast<float2*>(&kvout[(r0 + 8) * 64 + n0 + j * 8 + c0]) =
            make_float2(acc[j][2], acc[j][3]);
    }
    if (wn == 1 && (lane & 3) == 0) {
        float* ksout = g_KS2 + ((size_t)split * 64 + bh) * 64;
        ksout[m0 + (lane >> 2)]     = accS[0];
        ksout[m0 + 8 + (lane >> 2)] = accS[2];
    }
}

// ---------------------------------------------------------------------------
// out[t,e] = q[t,e] + (sum_d q[t,d]*kv[d,e]) / (sum_d q[t,d]*ksum[d])
// Q fp16 in, fp16 out for proj GEMM. kv/ks summed from KVSPL split buffers.
// ---------------------------------------------------------------------------
__global__ __launch_bounds__(256) void attn_kernel()
{
    const int bh = blockIdx.y;
    const int b = bh / NH, h = bh % NH;
    const int t0 = blockIdx.x * 32;

    __shared__ float kvs[ND][ND];
    __shared__ float kss[ND];
    __shared__ float qs[32][ND];

    const int tid = threadIdx.x;
    #pragma unroll
    for (int i = 0; i < 4; i++) {
        int idx = i * 256 + tid;
        int rw = idx >> 4, c4 = (idx & 15) << 2;
        float4 s = make_float4(0.f, 0.f, 0.f, 0.f);
        #pragma unroll
        for (int sp = 0; sp < KVSPL; sp++) {
            const float* kvp = g_KV2 + ((size_t)sp * 64 + bh) * 4096;
            float4 a = *reinterpret_cast<const float4*>(kvp + rw * 64 + c4);
            s.x += a.x; s.y += a.y; s.z += a.z; s.w += a.w;
        }
        kvs[rw][c4] = s.x; kvs[rw][c4+1] = s.y; kvs[rw][c4+2] = s.z; kvs[rw][c4+3] = s.w;
    }
    if (tid < 64) {
        float s = 0.f;
        #pragma unroll
        for (int sp = 0; sp < KVSPL; sp++) s += g_KS2[(sp * 64 + bh) * 64 + tid];
        kss[tid] = s;
    }

    const __half* qp = g_Q + ((size_t)b * NT + t0) * NC + h * ND;
    {
        int rw = tid >> 3, c8 = (tid & 7) * 8;
        uint4 raw = *reinterpret_cast<const uint4*>(qp + (size_t)rw * NC + c8);
        const __half2* hp = reinterpret_cast<const __half2*>(&raw);
        #pragma unroll
        for (int j = 0; j < 4; j++) {
            float2 f = __half22float2(hp[j]);
            qs[rw][c8 + 2*j] = f.x; qs[rw][c8 + 2*j + 1] = f.y;
        }
    }
    __syncthreads();

    const int e = tid & 63, tg = tid >> 6;
    for (int tt = tg; tt < 32; tt += 4) {
        float ds = 0.f, os = 0.f;
        #pragma unroll
        for (int d = 0; d < ND; d++) {
            float qd = qs[tt][d];
            ds = fmaf(qd, kss[d], ds);
            os = fmaf(qd, kvs[d][e], os);
        }
        float val = qs[tt][e] + os / ds;
        g_a16[((size_t)b * NT + t0 + tt) * NC + h * ND + e] = __float2half_rn(val);
    }
}

// ---------------------------------------------------------------------------
extern "C" void kernel_launch(void* const* d_in, const int* in_sizes, int n_in,
                              void* d_out, int out_size)
{
    const float* x  = (const float*)d_in[0];
    const float* y  = (const float*)d_in[1];
    const float* Wq = (const float*)d_in[2];
    const float* bq = (const float*)d_in[3];
    const float* Wk = (const float*)d_in[4];
    const float* bk = (const float*)d_in[5];
    const float* Wv = (const float*)d_in[6];
    const float* bv = (const float*)d_in[7];
    const float* Wp = (const float*)d_in[8];
    const float* bp = (const float*)d_in[9];
    float* out = (float*)d_out;
    (void)in_sizes; (void)n_in; (void)out_size;

    cudaFuncSetAttribute(qkv_gemm,  cudaFuncAttributeMaxDynamicSharedMemorySize, GSMEM);
    cudaFuncSetAttribute(proj_gemm, cudaFuncAttributeMaxDynamicSharedMemorySize, GSMEM);
    cudaFuncSetAttribute(kv_hmma,   cudaFuncAttributeMaxDynamicSharedMemorySize, KV_SMEM);

    // 1. fp32 -> fp16 (merged)
    convert_act<<<dim3(NM * NC / 8 / 256, 2), 256>>>(x, y);
    convert_w<<<dim3(NC * NC / 8 / 256, 4), 256>>>(Wq, Wk, Wv, Wp);

    // 2. Q/K/V projections (softmax fused for Q,K) -> fp16
    qkv_gemm<<<dim3(NC / BN, NM / BM, 3), 256, GSMEM>>>(bq, bk, bv);

    // 3. kv = K^T V (+ksum via ones column) on tensor cores, 4-way T split
    kv_hmma<<<dim3(NB * NH, KVSPL), 256, KV_SMEM>>>();

    // 4. linear-attention combine -> fp16 for proj GEMM
    attn_kernel<<<dim3(NT / 32, NB * NH), 256>>>();

    // 5. output projection -> d_out (fp32)
    proj_gemm<<<dim3(NC / BN, NM / BM, 1), 256, GSMEM>>>(bp, out);
}

// round 10
// speedup vs baseline: 5.6523x; 1.2648x over previous
#include <cuda_runtime.h>
#include <cuda_fp16.h>
#include <cstdint>

#define NB 4
#define NT 4096
#define NC 1024
#define NH 16
#define ND 64
#define NM (NB*NT)          // 16384 rows
#define KVSPL 4

// ---------------------------------------------------------------------------
// Device global scratch (allocation-free requirement)
// ---------------------------------------------------------------------------
__device__ __half g_x16[(size_t)NM*NC];
__device__ __half g_y16[(size_t)NM*NC];
__device__ __half g_a16[(size_t)NM*NC];
__device__ __half g_wq[NC*NC];
__device__ __half g_wk[NC*NC];
__device__ __half g_wv[NC*NC];
__device__ __half g_wp[NC*NC];
__device__ __half g_Q[(size_t)NM*NC];
__device__ __half g_K[(size_t)NM*NC];
__device__ __half g_V[(size_t)NM*NC];
__device__ float g_KV2[KVSPL*64*64*64];   // [split][bh][d][e]
__device__ float g_KS2[KVSPL*64*64];      // [split][bh][d]
__device__ __half g_KVT[(size_t)64*5760]; // [bh][80 rows x 72 halfs]: rows 0-63 kv^T[e][d], row 64 ksum

// ---------------------------------------------------------------------------
// PTX helpers (sm_80+ portable: cp.async / ldmatrix / mma.sync)
// ---------------------------------------------------------------------------
__device__ __forceinline__ uint32_t smem_to_u32(const void* p) {
    uint32_t a;
    asm("{ .reg .u64 t; cvta.to.shared.u64 t, %1; cvt.u32.u64 %0, t; }" : "=r"(a) : "l"(p));
    return a;
}
__device__ __forceinline__ void cp16(uint32_t s, const void* g) {
    asm volatile("cp.async.cg.shared.global [%0], [%1], 16;" :: "r"(s), "l"(g));
}
__device__ __forceinline__ void cp_commit() { asm volatile("cp.async.commit_group;" ::: "memory"); }
template<int N> __device__ __forceinline__ void cp_wait() {
    asm volatile("cp.async.wait_group %0;" :: "n"(N) : "memory");
}
__device__ __forceinline__ void ldm_x4(uint32_t addr, uint32_t* r) {
    asm volatile("ldmatrix.sync.aligned.m8n8.x4.shared.b16 {%0,%1,%2,%3}, [%4];"
                 : "=r"(r[0]), "=r"(r[1]), "=r"(r[2]), "=r"(r[3]) : "r"(addr));
}
__device__ __forceinline__ void ldm_x4_t(uint32_t addr, uint32_t* r) {
    asm volatile("ldmatrix.sync.aligned.m8n8.x4.trans.shared.b16 {%0,%1,%2,%3}, [%4];"
                 : "=r"(r[0]), "=r"(r[1]), "=r"(r[2]), "=r"(r[3]) : "r"(addr));
}
__device__ __forceinline__ void mma_f16(float* d, const uint32_t* a, const uint32_t* b) {
    asm volatile("mma.sync.aligned.m16n8k16.row.col.f32.f16.f16.f32 "
                 "{%0,%1,%2,%3}, {%4,%5,%6,%7}, {%8,%9}, {%0,%1,%2,%3};"
                 : "+f"(d[0]), "+f"(d[1]), "+f"(d[2]), "+f"(d[3])
                 : "r"(a[0]), "r"(a[1]), "r"(a[2]), "r"(a[3]), "r"(b[0]), "r"(b[1]));
}

// softmax over 64 cols: 16 values per lane + quad reduction (xor 1, 2)
__device__ __forceinline__ void softmax16(float* v) {
    float mx = v[0];
    #pragma unroll
    for (int j = 1; j < 16; j++) mx = fmaxf(mx, v[j]);
    mx = fmaxf(mx, __shfl_xor_sync(0xffffffffu, mx, 1));
    mx = fmaxf(mx, __shfl_xor_sync(0xffffffffu, mx, 2));
    float s = 0.f;
    #pragma unroll
    for (int j = 0; j < 16; j++) { v[j] = __expf(v[j] - mx); s += v[j]; }
    s += __shfl_xor_sync(0xffffffffu, s, 1);
    s += __shfl_xor_sync(0xffffffffu, s, 2);
    float inv = 1.f / s;
    #pragma unroll
    for (int j = 0; j < 16; j++) v[j] *= inv;
}

// ---------------------------------------------------------------------------
// fp16 GEMM: Out[m,n] = sum_k A[m,k]*W[n,k] + bias[n], opt. softmax per 64.
// CTA 128(M) x 128(N), BK=32, 5-stage cp.async pipeline; 8 warps as 4(M)x2(N)
// with 32x64 warp tiles; 2 CTAs/SM (bubble covering).
// One __syncthreads per kt: stage kt+4 (== kt-1 mod 5) is safe to overwrite
// after the barrier since all warps finished reading it in iteration kt-1.
// ---------------------------------------------------------------------------
#define BM 128
#define BN 128
#define BK 32
#define STAGES 5
#define NKT (NC/BK)                // 32
#define SROW 40                    // padded row length in halfwords
#define AMAT (128*SROW*2)          // 10240
#define OFF_B AMAT
#define STG_BYTES (2*AMAT)         // 20480
#define GSMEM (STAGES*STG_BYTES)   // 102400

__device__ __forceinline__ void gemm_body(
    const __half* __restrict__ A16, const __half* __restrict__ B16,
    const float* __restrict__ bias, float* __restrict__ OutF,
    __half* __restrict__ OutH, int do_softmax)
{
    extern __shared__ __align__(128) char sm[];
    uint32_t smb = smem_to_u32(sm);
    const int tid = threadIdx.x;
    const int m0 = blockIdx.y * BM, n0 = blockIdx.x * BN;

    const __half* a_g = A16 + (size_t)m0 * NC;
    const __half* b_g = B16 + (size_t)n0 * NC;

    auto issue = [&](int stage, int k0) {
        uint32_t sb = smb + stage * STG_BYTES;
        #pragma unroll
        for (int i = 0; i < 2; i++) {                 // A and B: 512 cp16 each
            int g = i * 256 + tid;
            int row = g >> 2, c = g & 3;
            uint32_t so = row * (SROW * 2) + c * 16;
            size_t  go = (size_t)row * NC + k0 + c * 8;
            cp16(sb + so,         a_g + go);
            cp16(sb + OFF_B + so, b_g + go);
        }
    };

    #pragma unroll
    for (int s = 0; s < STAGES - 1; s++) { issue(s, s * BK); cp_commit(); }

    const int wid = tid >> 5, lane = tid & 31;
    const int wm = wid & 3, wn = wid >> 2;            // warp tile: 32(M) x 64(N)

    float acc[2][8][4];
    #pragma unroll
    for (int a = 0; a < 2; a++)
        #pragma unroll
        for (int b = 0; b < 8; b++)
            #pragma unroll
            for (int c = 0; c < 4; c++) acc[a][b][c] = 0.f;

    const int a_row = wm * 32 + (lane & 7) + ((lane >> 3) & 1) * 8;   // + mt*16
    const int b_row = wn * 64 + (lane & 15);                           // + p*16
    const int colb  = (lane >> 4) * 16;                                // + ks*32

    for (int kt = 0; kt < NKT; kt++) {
        cp_wait<STAGES - 2>();
        __syncthreads();
        if (kt + STAGES - 1 < NKT) issue((kt + STAGES - 1) % STAGES, (kt + STAGES - 1) * BK);
        cp_commit();
        uint32_t sb = smb + (kt % STAGES) * STG_BYTES;
        #pragma unroll
        for (int ks = 0; ks < 2; ks++) {
            uint32_t ah[2][4];
            #pragma unroll
            for (int mt = 0; mt < 2; mt++)
                ldm_x4(sb + (a_row + mt * 16) * (SROW * 2) + ks * 32 + colb, ah[mt]);
            uint32_t bh[8][2];
            #pragma unroll
            for (int p = 0; p < 4; p++) {
                uint32_t t[4];
                ldm_x4(sb + OFF_B + (b_row + p * 16) * (SROW * 2) + ks * 32 + colb, t);
                bh[2*p][0] = t[0]; bh[2*p+1][0] = t[1]; bh[2*p][1] = t[2]; bh[2*p+1][1] = t[3];
            }
            #pragma unroll
            for (int mt = 0; mt < 2; mt++)
                #pragma unroll
                for (int nt = 0; nt < 8; nt++) mma_f16(acc[mt][nt], ah[mt], bh[nt]);
        }
    }

    // ---- Epilogue: bias (+softmax per 64-wide head) + store ----
    float2 bias2[8];
    const int cb = n0 + wn * 64 + (lane & 3) * 2;
    #pragma unroll
    for (int nt = 0; nt < 8; nt++)
        bias2[nt] = *reinterpret_cast<const float2*>(&bias[cb + nt * 8]);

    #pragma unroll
    for (int mt = 0; mt < 2; mt++) {
        float va[16], vb[16];
        #pragma unroll
        for (int nt = 0; nt < 8; nt++) {
            va[2*nt]   = acc[mt][nt][0] + bias2[nt].x;
            va[2*nt+1] = acc[mt][nt][1] + bias2[nt].y;
            vb[2*nt]   = acc[mt][nt][2] + bias2[nt].x;
            vb[2*nt+1] = acc[mt][nt][3] + bias2[nt].y;
        }
        if (do_softmax) { softmax16(va); softmax16(vb); }
        const int rowa = m0 + wm * 32 + mt * 16 + (lane >> 2);
        const int rowb = rowa + 8;
        if (OutH) {
            #pragma unroll
            for (int nt = 0; nt < 8; nt++) {
                *reinterpret_cast<__half2*>(&OutH[(size_t)rowa * NC + cb + nt * 8]) =
                    __floats2half2_rn(va[2*nt], va[2*nt+1]);
                *reinterpret_cast<__half2*>(&OutH[(size_t)rowb * NC + cb + nt * 8]) =
                    __floats2half2_rn(vb[2*nt], vb[2*nt+1]);
            }
        } else {
            #pragma unroll
            for (int nt = 0; nt < 8; nt++) {
                *reinterpret_cast<float2*>(&OutF[(size_t)rowa * NC + cb + nt * 8]) =
                    make_float2(va[2*nt], va[2*nt+1]);
                *reinterpret_cast<float2*>(&OutF[(size_t)rowb * NC + cb + nt * 8]) =
                    make_float2(vb[2*nt], vb[2*nt+1]);
            }
        }
    }
}

__global__ __launch_bounds__(256, 2) void qkv_gemm(
    const float* __restrict__ bq, const float* __restrict__ bk, const float* __restrict__ bv)
{
    int z = blockIdx.z;
    if (z == 0)      gemm_body(g_x16, g_wq, bq, nullptr, g_Q, 1);
    else if (z == 1) gemm_body(g_y16, g_wk, bk, nullptr, g_K, 1);
    else             gemm_body(g_y16, g_wv, bv, nullptr, g_V, 0);
}

__global__ __launch_bounds__(256, 2) void proj_gemm(
    const float* __restrict__ bp, float* __restrict__ out)
{
    gemm_body(g_a16, g_wp, bp, out, nullptr, 0);
}

// ---------------------------------------------------------------------------
// fp32 -> fp16 converts (merged launches)
// ---------------------------------------------------------------------------
__global__ __launch_bounds__(256) void convert_act(const float* __restrict__ x,
                                                   const float* __restrict__ y)
{
    const float* src = blockIdx.y ? y : x;
    __half* dh = blockIdx.y ? g_y16 : g_x16;
    int g = blockIdx.x * 256 + threadIdx.x;
    const float4* p = reinterpret_cast<const float4*>(src) + (size_t)g * 2;
    float4 a = p[0], b = p[1];
    alignas(16) __half h[8] = {
        __float2half_rn(a.x), __float2half_rn(a.y), __float2half_rn(a.z), __float2half_rn(a.w),
        __float2half_rn(b.x), __float2half_rn(b.y), __float2half_rn(b.z), __float2half_rn(b.w) };
    *reinterpret_cast<uint4*>(dh + (size_t)g * 8) = *reinterpret_cast<uint4*>(h);
}

__global__ __launch_bounds__(256) void convert_w(const float* __restrict__ wq,
                                                 const float* __restrict__ wk,
                                                 const float* __restrict__ wv,
                                                 const float* __restrict__ wp)
{
    const float* src; __half* dh;
    switch (blockIdx.y) {
        case 0: src = wq; dh = g_wq; break;
        case 1: src = wk; dh = g_wk; break;
        case 2: src = wv; dh = g_wv; break;
        default: src = wp; dh = g_wp; break;
    }
    int g = blockIdx.x * 256 + threadIdx.x;
    const float4* p = reinterpret_cast<const float4*>(src) + (size_t)g * 2;
    float4 a = p[0], b = p[1];
    alignas(16) __half h[8] = {
        __float2half_rn(a.x), __float2half_rn(a.y), __float2half_rn(a.z), __float2half_rn(a.w),
        __float2half_rn(b.x), __float2half_rn(b.y), __float2half_rn(b.z), __float2half_rn(b.w) };
    *reinterpret_cast<uint4*>(dh + (size_t)g * 8) = *reinterpret_cast<uint4*>(h);
}

// ---------------------------------------------------------------------------
// kv via HMMA: kv[d][e] = sum_n K[n,d]*V[n,e]; ksum[d] = sum_n K[n,d]
// grid (64 bh, KVSPL splits), 256 thr (8 warps as 4(d) x 2(e)).
// ---------------------------------------------------------------------------
#define KV_ROW 176                 // bytes per smem row (88 halfs)
#define KV_MAT (128*KV_ROW)        // 22528
#define KV_STG (2*KV_MAT)          // 45056 (K then V)
#define KV_SMEM (2*KV_STG)         // 90112
#define KV_TILES (NT/KVSPL/128)    // 8

__global__ __launch_bounds__(256, 1) void kv_hmma()
{
    extern __shared__ __align__(128) char sm[];
    uint32_t smb = smem_to_u32(sm);
    const int bh = blockIdx.x, split = blockIdx.y;
    const int tid = threadIdx.x, wid = tid >> 5, lane = tid & 31;
    const int wm = wid & 3, wn = wid >> 2;
    const int m0 = wm * 16, n0 = wn * 32;
    const int lr = lane & 7, lg = lane >> 3;

    const __half* Kp = g_K + (size_t)(bh / NH) * NT * NC + (bh % NH) * ND;
    const __half* Vp = g_V + (size_t)(bh / NH) * NT * NC + (bh % NH) * ND;
    const int tokbase = split * (NT / KVSPL);

    auto issue = [&](int stage, int tile) {
        uint32_t sb = smb + stage * KV_STG;
        int t0 = tokbase + tile * 128;
        #pragma unroll
        for (int i = 0; i < 4; i++) {
            int slot = i * 256 + tid;
            int row = slot >> 3, c = slot & 7;
            cp16(sb + row * KV_ROW + c * 16,          Kp + (size_t)(t0 + row) * NC + c * 8);
            cp16(sb + KV_MAT + row * KV_ROW + c * 16, Vp + (size_t)(t0 + row) * NC + c * 8);
        }
        int row = tid >> 1, which = tid & 1;
        uint4 padv = which ? make_uint4(0u, 0u, 0u, 0u)
                           : make_uint4(0x00003C00u, 0u, 0u, 0u);
        *reinterpret_cast<uint4*>(sm + stage * KV_STG + KV_MAT + row * KV_ROW + 128 + which * 16) = padv;
    };

    float acc[4][4] = {};
    float accS[4]   = {};

    issue(0, 0); cp_commit();

    for (int tile = 0; tile < KV_TILES; tile++) {
        if (tile + 1 < KV_TILES) { issue((tile + 1) & 1, tile + 1); cp_commit(); cp_wait<1>(); }
        else cp_wait<0>();
        __syncthreads();
        uint32_t kb = smb + (tile & 1) * KV_STG;
        uint32_t vb = kb + KV_MAT;
        #pragma unroll
        for (int s = 0; s < 8; s++) {
            int ts = s * 16;
            uint32_t a[4];
            ldm_x4_t(kb + (ts + lr + (lg >> 1) * 8) * KV_ROW + (m0 + (lg & 1) * 8) * 2, a);
            #pragma unroll
            for (int eg = 0; eg < 2; eg++) {
                uint32_t t[4];
                ldm_x4_t(vb + (ts + lr + (lg & 1) * 8) * KV_ROW + (n0 + eg * 16 + (lg >> 1) * 8) * 2, t);
                mma_f16(acc[eg * 2 + 0], a, t + 0);
                mma_f16(acc[eg * 2 + 1], a, t + 2);
            }
            if (wn == 1) {
                uint32_t t[4];
                ldm_x4_t(vb + (ts + lr + (lg & 1) * 8) * KV_ROW + (64 + (lg >> 1) * 8) * 2, t);
                mma_f16(accS, a, t + 0);
            }
        }
        __syncthreads();
    }

    float* kvout = g_KV2 + ((size_t)split * 64 + bh) * 4096;
    const int r0 = m0 + (lane >> 2), c0 = (lane & 3) * 2;
    #pragma unroll
    for (int j = 0; j < 4; j++) {
        *reinterpret_cast<float2*>(&kvout[r0 * 64 + n0 + j * 8 + c0]) =
            make_float2(acc[j][0], acc[j][1]);
        *reinterpret_cast<float2*>(&kvout[(r0 + 8) * 64 + n0 + j * 8 + c0]) =
            make_float2(acc[j][2], acc[j][3]);
    }
    if (wn == 1 && (lane & 3) == 0) {
        float* ksout = g_KS2 + ((size_t)split * 64 + bh) * 64;
        ksout[m0 + (lane >> 2)]     = accS[0];
        ksout[m0 + 8 + (lane >> 2)] = accS[2];
    }
}

// ---------------------------------------------------------------------------
// kv_reduce: sum KVSPL splits -> fp16 kv^T tile [80 rows x 72 halfs] per bh:
//   rows 0-63: kvT[e][d] = kv[d][e]; row 64: ksum[d]; rows 65-71: zero.
//   (rows 72-79 exist for ldmatrix address validity; values unused.)
// ---------------------------------------------------------------------------
__global__ __launch_bounds__(256) void kv_reduce()
{
    const int bh = blockIdx.x, tid = threadIdx.x;
    __half* dst = g_KVT + (size_t)bh * 5760;
    #pragma unroll
    for (int i = 0; i < 16; i++) {
        int idx = i * 256 + tid;
        int d = idx >> 6, e = idx & 63;
        float s = 0.f;
        #pragma unroll
        for (int sp = 0; sp < KVSPL; sp++)
            s += g_KV2[((size_t)sp * 64 + bh) * 4096 + idx];
        dst[e * 72 + d] = __float2half_rn(s);
    }
    if (tid < 64) {
        float s = 0.f;
        #pragma unroll
        for (int sp = 0; sp < KVSPL; sp++) s += g_KS2[(sp * 64 + bh) * 64 + tid];
        dst[64 * 72 + tid] = __float2half_rn(s);
    }
    // zero row 64 cols 64-71 and rows 65-71 (8 + 504 halfs)
    for (int j = tid; j < 512; j += 256) dst[64 * 72 + 64 + j] = __float2half_rn(0.f);
}

// ---------------------------------------------------------------------------
// attn via HMMA: os[t,e] = sum_d q[t,d]*kvT[e,d]; ds[t] from ksum row (n=64).
// out[t,e] = q[t,e] + os/ds -> fp16 for proj GEMM.
// grid (NT/128, 64 bh), 256 thr; warp wid = tokens wid*16..+15, full N=64.
// ---------------------------------------------------------------------------
#define AT_ROW 144   // 72 halfs per smem row

__global__ __launch_bounds__(256) void attn_hmma()
{
    __shared__ __align__(16) char sq[128 * AT_ROW];  // Q tile: 128 tok x 64 d
    __shared__ __align__(16) char sb[80 * AT_ROW];   // kvT + ksum tile
    const int bh = blockIdx.y, b = bh / NH, h = bh % NH;
    const int t0 = blockIdx.x * 128;
    const int tid = threadIdx.x, wid = tid >> 5, lane = tid & 31;
    uint32_t sqb = smem_to_u32(sq), sbb = smem_to_u32(sb);

    const __half* Qp = g_Q + ((size_t)b * NT + t0) * NC + h * ND;
    #pragma unroll
    for (int i = 0; i < 4; i++) {                     // 1024 cp16
        int slot = i * 256 + tid;
        int row = slot >> 3, c = slot & 7;
        cp16(sqb + row * AT_ROW + c * 16, Qp + (size_t)row * NC + c * 8);
    }
    const __half* Bp = g_KVT + (size_t)bh * 5760;     // 720 cp16
    for (int s = tid; s < 720; s += 256) cp16(sbb + s * 16, Bp + s * 8);
    cp_commit(); cp_wait<0>();
    __syncthreads();

    float acc[9][4] = {};                              // 8 n-tiles + ksum tile
    const int a_row = wid * 16 + (lane & 7) + ((lane >> 3) & 1) * 8;
    const int b_row = lane & 15;
    const int colb  = (lane >> 4) * 16;

    #pragma unroll
    for (int ks = 0; ks < 4; ks++) {
        uint32_t a[4];
        ldm_x4(sqb + a_row * AT_ROW + ks * 32 + colb, a);
        #pragma unroll
        for (int p = 0; p < 5; p++) {
            uint32_t t[4];
            ldm_x4(sbb + (b_row + p * 16) * AT_ROW + ks * 32 + colb, t);
            uint32_t f0[2] = { t[0], t[2] };
            mma_f16(acc[2 * p], a, f0);
            if (p < 4) {
                uint32_t f1[2] = { t[1], t[3] };
                mma_f16(acc[2 * p + 1], a, f1);
            }
        }
    }

    // ds broadcast: n=64 column lives in lane&3==0, regs 0 (row r) / 2 (row r+8)
    float ds0 = __shfl_sync(0xffffffffu, acc[8][0], lane & ~3);
    float ds1 = __shfl_sync(0xffffffffu, acc[8][2], lane & ~3);
    ds0 = 1.f / ds0; ds1 = 1.f / ds1;

    const int r = wid * 16 + (lane >> 2);
    const int cb = (lane & 3) * 2;
    __half* outp = g_a16 + ((size_t)b * NT + t0) * NC + h * ND;
    #pragma unroll
    for (int nt = 0; nt < 8; nt++) {
        int e = nt * 8 + cb;
        __half2 q0 = *reinterpret_cast<const __half2*>(sq + r * AT_ROW + e * 2);
        __half2 q1 = *reinterpret_cast<const __half2*>(sq + (r + 8) * AT_ROW + e * 2);
        float2 qf0 = __half22float2(q0), qf1 = __half22float2(q1);
        *reinterpret_cast<__half2*>(outp + (size_t)r * NC + e) =
            __floats2half2_rn(qf0.x + acc[nt][0] * ds0, qf0.y + acc[nt][1] * ds0);
        *reinterpret_cast<__half2*>(outp + (size_t)(r + 8) * NC + e) =
            __floats2half2_rn(qf1.x + acc[nt][2] * ds1, qf1.y + acc[nt][3] * ds1);
    }
}

// ---------------------------------------------------------------------------
extern "C" void kernel_launch(void* const* d_in, const int* in_sizes, int n_in,
                              void* d_out, int out_size)
{
    const float* x  = (const float*)d_in[0];
    const float* y  = (const float*)d_in[1];
    const float* Wq = (const float*)d_in[2];
    const float* bq = (const float*)d_in[3];
    const float* Wk = (const float*)d_in[4];
    const float* bk = (const float*)d_in[5];
    const float* Wv = (const float*)d_in[6];
    const float* bv = (const float*)d_in[7];
    const float* Wp = (const float*)d_in[8];
    const float* bp = (const float*)d_in[9];
    float* out = (float*)d_out;
    (void)in_sizes; (void)n_in; (void)out_size;

    cudaFuncSetAttribute(qkv_gemm,  cudaFuncAttributeMaxDynamicSharedMemorySize, GSMEM);
    cudaFuncSetAttribute(proj_gemm, cudaFuncAttributeMaxDynamicSharedMemorySize, GSMEM);
    cudaFuncSetAttribute(kv_hmma,   cudaFuncAttributeMaxDynamicSharedMemorySize, KV_SMEM);

    // 1. fp32 -> fp16 (merged)
    convert_act<<<dim3(NM * NC / 8 / 256, 2), 256>>>(x, y);
    convert_w<<<dim3(NC * NC / 8 / 256, 4), 256>>>(Wq, Wk, Wv, Wp);

    // 2. Q/K/V projections (softmax fused for Q,K) -> fp16
    qkv_gemm<<<dim3(NC / BN, NM / BM, 3), 256, GSMEM>>>(bq, bk, bv);

    // 3. kv = K^T V (+ksum) on tensor cores, 4-way T split, then fp16 reduce
    kv_hmma<<<dim3(NB * NH, KVSPL), 256, KV_SMEM>>>();
    kv_reduce<<<NB * NH, 256>>>();

    // 4. linear-attention combine on tensor cores -> fp16 for proj GEMM
    attn_hmma<<<dim3(NT / 128, NB * NH), 256>>>();

    // 5. output projection -> d_out (fp32)
    proj_gemm<<<dim3(NC / BN, NM / BM, 1), 256, GSMEM>>>(bp, out);
}